// round 2
// baseline (speedup 1.0000x reference)
#include <cuda_runtime.h>
#include <stdint.h>

// SimpleGCN: 2-layer GCN, N=100000 nodes, C=32 channels, E=1.6M edges.
// out = GCNConv2( relu( GCNConv1(x) ) ), self-loops added, symmetric norm.
//
// NOTE: JAX x64 is disabled by default, so edge_index is int32 on device
// despite the reference saying jnp.int64.
//
// Inputs (metadata order):
//   d_in[0] = x          float32 [N*32]
//   d_in[1] = edge_index int32   [2*E]  (rows = [0:E), cols = [E:2E))
//   d_in[2] = W1 float32 [32*32]  d_in[3] = b1 float32 [32]
//   d_in[4] = W2 float32 [32*32]  d_in[5] = b2 float32 [32]
// Output: float32 [N*32]

#define GCN_N 100000
#define GCN_C 32

// Scratch (device globals: no allocation allowed in kernel_launch)
__device__ float g_dis[GCN_N];                         // deg -> rsqrt(deg)
__device__ __align__(16) float g_h1[GCN_N * GCN_C];    // x @ W1
__device__ __align__(16) float g_o1[GCN_N * GCN_C];    // layer-1 output acc
__device__ __align__(16) float g_h2[GCN_N * GCN_C];    // relu(o1) @ W2

// ---------------------------------------------------------------------------
// Degree kernels
// ---------------------------------------------------------------------------
__global__ void k_deg_init(float* __restrict__ deg, int n) {
    int i = blockIdx.x * blockDim.x + threadIdx.x;
    if (i < n) deg[i] = 1.0f;  // self-loop contributes 1
}

__global__ void k_deg_acc(const int* __restrict__ col, float* __restrict__ deg, int E) {
    int e = blockIdx.x * blockDim.x + threadIdx.x;
    if (e < E) atomicAdd(&deg[col[e]], 1.0f);  // result unused -> RED
}

__global__ void k_dis(float* __restrict__ deg, int n) {
    int i = blockIdx.x * blockDim.x + threadIdx.x;
    if (i < n) deg[i] = rsqrtf(deg[i]);  // deg >= 1 always
}

// ---------------------------------------------------------------------------
// Fused GEMM + self-loop/bias init:
//   h[n,c]   = (relu?) x[n,:] @ W[:,c]
//   out[n,c] = b[c] + dis[n]^2 * h[n,c]
// One warp per node; W staged in shared (padded to kill bank conflicts).
// ---------------------------------------------------------------------------
template <bool RELU_IN>
__global__ __launch_bounds__(256) void k_gemm_init(
    const float* __restrict__ x, const float* __restrict__ W,
    const float* __restrict__ b, const float* __restrict__ dis,
    float* __restrict__ h, float* __restrict__ out, int n)
{
    __shared__ float Ws[32][33];
    __shared__ float bs[32];
    int t = threadIdx.x;
    for (int i = t; i < 32 * 32; i += blockDim.x) Ws[i >> 5][i & 31] = W[i];
    if (t < 32) bs[t] = b[t];
    __syncthreads();

    int lane = t & 31;
    int warp = t >> 5;
    int warps_per_blk = blockDim.x >> 5;
    int node = blockIdx.x * warps_per_blk + warp;
    int stride = gridDim.x * warps_per_blk;

    for (; node < n; node += stride) {
        float xv = x[node * GCN_C + lane];
        if (RELU_IN) xv = fmaxf(xv, 0.0f);
        float acc = 0.0f;
        #pragma unroll
        for (int k = 0; k < 32; k++)
            acc = fmaf(__shfl_sync(0xffffffffu, xv, k), Ws[k][lane], acc);
        h[node * GCN_C + lane] = acc;
        float d = dis[node];
        out[node * GCN_C + lane] = fmaf(d * d, acc, bs[lane]);
    }
}

// ---------------------------------------------------------------------------
// Edge scatter: 8 lanes per edge, each lane does one float4 vector reduction.
//   out[col, :] += dis[row]*dis[col] * h[row, :]
// ---------------------------------------------------------------------------
__global__ __launch_bounds__(256) void k_scatter(
    const int* __restrict__ row, const int* __restrict__ col,
    const float* __restrict__ dis, const float* __restrict__ h,
    float* __restrict__ out, int E)
{
    long long tid = (long long)blockIdx.x * blockDim.x + threadIdx.x;
    int e = (int)(tid >> 3);
    if (e >= E) return;
    int sub = (int)(tid & 7);

    int r = row[e];
    int c = col[e];
    float norm = dis[r] * dis[c];

    const float4 v = __ldg(reinterpret_cast<const float4*>(h + (long long)r * GCN_C + sub * 4));
    float4 m;
    m.x = v.x * norm; m.y = v.y * norm; m.z = v.z * norm; m.w = v.w * norm;

    float* p = out + (long long)c * GCN_C + sub * 4;
    asm volatile("red.global.add.v4.f32 [%0], {%1, %2, %3, %4};"
                 :: "l"(p), "f"(m.x), "f"(m.y), "f"(m.z), "f"(m.w)
                 : "memory");
}

// ---------------------------------------------------------------------------
// Launch
// ---------------------------------------------------------------------------
extern "C" void kernel_launch(void* const* d_in, const int* in_sizes, int n_in,
                              void* d_out, int out_size)
{
    const float* x    = (const float*)d_in[0];
    const int*   ei   = (const int*)d_in[1];
    const float* W1   = (const float*)d_in[2];
    const float* b1   = (const float*)d_in[3];
    const float* W2   = (const float*)d_in[4];
    const float* b2   = (const float*)d_in[5];
    float*       outp = (float*)d_out;

    const int E = in_sizes[1] / 2;
    const int* rows = ei;
    const int* cols = ei + E;
    const int n = GCN_N;

    float *p_dis, *p_h1, *p_o1, *p_h2;
    cudaGetSymbolAddress((void**)&p_dis, g_dis);
    cudaGetSymbolAddress((void**)&p_h1,  g_h1);
    cudaGetSymbolAddress((void**)&p_o1,  g_o1);
    cudaGetSymbolAddress((void**)&p_h2,  g_h2);

    const int T = 256;

    // degrees -> dis
    k_deg_init<<<(n + T - 1) / T, T>>>(p_dis, n);
    k_deg_acc<<<(E + T - 1) / T, T>>>(cols, p_dis, E);
    k_dis<<<(n + T - 1) / T, T>>>(p_dis, n);

    // layer 1: h1 = x@W1 ; o1 = b1 + dis^2*h1 ; scatter edges
    k_gemm_init<false><<<(n + 7) / 8, T>>>(x, W1, b1, p_dis, p_h1, p_o1, n);
    k_scatter<<<(int)(((long long)E * 8 + T - 1) / T), T>>>(rows, cols, p_dis, p_h1, p_o1, E);

    // layer 2: h2 = relu(o1)@W2 ; out = b2 + dis^2*h2 ; scatter edges
    k_gemm_init<true><<<(n + 7) / 8, T>>>(p_o1, W2, b2, p_dis, p_h2, outp, n);
    k_scatter<<<(int)(((long long)E * 8 + T - 1) / T), T>>>(rows, cols, p_dis, p_h2, outp, E);
}

// round 3
// speedup vs baseline: 1.2210x; 1.2210x over previous
#include <cuda_runtime.h>
#include <stdint.h>

// SimpleGCN: 2-layer GCN, N=100000 nodes, C=32 channels, E=1.6M edges (int32).
// out = GCNConv2( relu( GCNConv1(x) ) ), self-loops, symmetric norm.
//
// Inputs: x f32[N*32], edge_index i32[2*E] (rows then cols),
//         W1 f32[32*32], b1 f32[32], W2 f32[32*32], b2 f32[32]
// Output: f32[N*32]

#define GCN_N 100000
#define GCN_C 32
#define GCN_EMAX 1600000

__device__ float g_dis[GCN_N];                          // deg -> rsqrt(deg)
__device__ float g_norm[GCN_EMAX];                      // per-edge dis[r]*dis[c]
__device__ __align__(16) float g_h1[GCN_N * GCN_C];     // x @ W1
__device__ __align__(16) float g_o1[GCN_N * GCN_C];     // layer-1 output acc
__device__ __align__(16) float g_h2[GCN_N * GCN_C];     // relu(o1) @ W2

// ---------------------------------------------------------------------------
// Degree / norm kernels
// ---------------------------------------------------------------------------
__global__ void k_deg_init(float* __restrict__ deg, int n) {
    int i = blockIdx.x * blockDim.x + threadIdx.x;
    if (i < n) deg[i] = 1.0f;  // self-loop contributes 1
}

__global__ void k_deg_acc(const int* __restrict__ col, float* __restrict__ deg, int E) {
    int e = blockIdx.x * blockDim.x + threadIdx.x;
    if (e < E) atomicAdd(&deg[col[e]], 1.0f);  // result unused -> RED
}

__global__ void k_dis(float* __restrict__ deg, int n) {
    int i = blockIdx.x * blockDim.x + threadIdx.x;
    if (i < n) deg[i] = rsqrtf(deg[i]);  // deg >= 1 always
}

__global__ void k_norm(const int* __restrict__ row, const int* __restrict__ col,
                       const float* __restrict__ dis, float* __restrict__ norm, int E) {
    int e = blockIdx.x * blockDim.x + threadIdx.x;
    if (e < E) norm[e] = dis[row[e]] * dis[col[e]];
}

// ---------------------------------------------------------------------------
// Register-tiled GEMM + self-loop/bias epilogue.
//   h[n,c]   = (relu?) x[n,:] @ W[:,c]
//   out[n,c] = b[c] + dis[n]^2 * h[n,c]
// Block: 256 threads, 128 nodes. Thread: 4 nodes x 4 channels register tile.
// x staged TRANSPOSED in shared (k-major, stride 132 -> conflict-free LDS.128).
// ---------------------------------------------------------------------------
template <bool RELU_IN>
__global__ __launch_bounds__(256) void k_gemm_tiled(
    const float* __restrict__ x, const float* __restrict__ W,
    const float* __restrict__ b, const float* __restrict__ dis,
    float* __restrict__ h, float* __restrict__ out, int n)
{
    __shared__ float xT[32][132];   // [k][node], padded stride
    __shared__ float Ws[32 * 32];   // row-major [k][c]
    __shared__ float bs[32];

    const int tid = threadIdx.x;
    const int base = blockIdx.x * 128;

    // Stage W (256 x float4 = 1024 floats) and bias
    ((float4*)Ws)[tid] = ((const float4*)W)[tid];
    if (tid < 32) bs[tid] = b[tid];

    // Stage x tile transposed: 128 nodes x 32 k = 1024 float4 loads / 256 thr
    #pragma unroll
    for (int l = 0; l < 4; l++) {
        int i = tid + l * 256;
        int node = i >> 3;          // 0..127
        int kc = (i & 7) * 4;       // 0,4,...,28
        float4 v = make_float4(0.f, 0.f, 0.f, 0.f);
        if (base + node < n)
            v = *(const float4*)(x + (size_t)(base + node) * GCN_C + kc);
        if (RELU_IN) {
            v.x = fmaxf(v.x, 0.f); v.y = fmaxf(v.y, 0.f);
            v.z = fmaxf(v.z, 0.f); v.w = fmaxf(v.w, 0.f);
        }
        xT[kc + 0][node] = v.x;
        xT[kc + 1][node] = v.y;
        xT[kc + 2][node] = v.z;
        xT[kc + 3][node] = v.w;
    }
    __syncthreads();

    const int tn = (tid & 31) * 4;  // node offset within tile
    const int tc = (tid >> 5) * 4;  // channel offset

    float4 a0 = {0,0,0,0}, a1 = {0,0,0,0}, a2 = {0,0,0,0}, a3 = {0,0,0,0};
    #pragma unroll
    for (int k = 0; k < 32; k++) {
        float4 a = *(const float4*)&xT[k][tn];
        float4 w = *(const float4*)&Ws[k * 32 + tc];
        a0.x = fmaf(a.x, w.x, a0.x); a0.y = fmaf(a.x, w.y, a0.y);
        a0.z = fmaf(a.x, w.z, a0.z); a0.w = fmaf(a.x, w.w, a0.w);
        a1.x = fmaf(a.y, w.x, a1.x); a1.y = fmaf(a.y, w.y, a1.y);
        a1.z = fmaf(a.y, w.z, a1.z); a1.w = fmaf(a.y, w.w, a1.w);
        a2.x = fmaf(a.z, w.x, a2.x); a2.y = fmaf(a.z, w.y, a2.y);
        a2.z = fmaf(a.z, w.z, a2.z); a2.w = fmaf(a.z, w.w, a2.w);
        a3.x = fmaf(a.w, w.x, a3.x); a3.y = fmaf(a.w, w.y, a3.y);
        a3.z = fmaf(a.w, w.z, a3.z); a3.w = fmaf(a.w, w.w, a3.w);
    }

    const float4 bias = *(const float4*)&bs[tc];
    float4 accs[4] = {a0, a1, a2, a3};
    #pragma unroll
    for (int i = 0; i < 4; i++) {
        int node = base + tn + i;
        if (node < n) {
            float d = dis[node];
            float dd = d * d;
            float4 acc = accs[i];
            *(float4*)(h + (size_t)node * GCN_C + tc) = acc;
            float4 o;
            o.x = fmaf(dd, acc.x, bias.x);
            o.y = fmaf(dd, acc.y, bias.y);
            o.z = fmaf(dd, acc.z, bias.z);
            o.w = fmaf(dd, acc.w, bias.w);
            *(float4*)(out + (size_t)node * GCN_C + tc) = o;
        }
    }
}

// ---------------------------------------------------------------------------
// Edge scatter: 8 lanes per edge, one float4 vector reduction each.
//   out[col, :] += norm[e] * h[row, :]
// ---------------------------------------------------------------------------
__global__ __launch_bounds__(256) void k_scatter(
    const int* __restrict__ row, const int* __restrict__ col,
    const float* __restrict__ norm, const float* __restrict__ h,
    float* __restrict__ out, int E)
{
    long long tid = (long long)blockIdx.x * blockDim.x + threadIdx.x;
    int e = (int)(tid >> 3);
    if (e >= E) return;
    int sub = (int)(tid & 7);

    int r = row[e];
    int c = col[e];
    float nrm = norm[e];

    const float4 v = __ldg((const float4*)(h + (size_t)r * GCN_C + sub * 4));
    float4 m;
    m.x = v.x * nrm; m.y = v.y * nrm; m.z = v.z * nrm; m.w = v.w * nrm;

    float* p = out + (size_t)c * GCN_C + sub * 4;
    asm volatile("red.global.add.v4.f32 [%0], {%1, %2, %3, %4};"
                 :: "l"(p), "f"(m.x), "f"(m.y), "f"(m.z), "f"(m.w)
                 : "memory");
}

// ---------------------------------------------------------------------------
// Launch
// ---------------------------------------------------------------------------
extern "C" void kernel_launch(void* const* d_in, const int* in_sizes, int n_in,
                              void* d_out, int out_size)
{
    const float* x    = (const float*)d_in[0];
    const int*   ei   = (const int*)d_in[1];
    const float* W1   = (const float*)d_in[2];
    const float* b1   = (const float*)d_in[3];
    const float* W2   = (const float*)d_in[4];
    const float* b2   = (const float*)d_in[5];
    float*       outp = (float*)d_out;

    const int E = in_sizes[1] / 2;
    const int* rows = ei;
    const int* cols = ei + E;
    const int n = GCN_N;

    float *p_dis, *p_norm, *p_h1, *p_o1, *p_h2;
    cudaGetSymbolAddress((void**)&p_dis,  g_dis);
    cudaGetSymbolAddress((void**)&p_norm, g_norm);
    cudaGetSymbolAddress((void**)&p_h1,   g_h1);
    cudaGetSymbolAddress((void**)&p_o1,   g_o1);
    cudaGetSymbolAddress((void**)&p_h2,   g_h2);

    const int T = 256;

    // degrees -> dis -> per-edge norm
    k_deg_init<<<(n + T - 1) / T, T>>>(p_dis, n);
    k_deg_acc<<<(E + T - 1) / T, T>>>(cols, p_dis, E);
    k_dis<<<(n + T - 1) / T, T>>>(p_dis, n);
    k_norm<<<(E + T - 1) / T, T>>>(rows, cols, p_dis, p_norm, E);

    const int gemm_grid = (n + 127) / 128;
    const int scat_grid = (int)(((long long)E * 8 + T - 1) / T);

    // layer 1
    k_gemm_tiled<false><<<gemm_grid, T>>>(x, W1, b1, p_dis, p_h1, p_o1, n);
    k_scatter<<<scat_grid, T>>>(rows, cols, p_norm, p_h1, p_o1, E);

    // layer 2
    k_gemm_tiled<true><<<gemm_grid, T>>>(p_o1, W2, b2, p_dis, p_h2, outp, n);
    k_scatter<<<scat_grid, T>>>(rows, cols, p_norm, p_h2, outp, E);
}

// round 4
// speedup vs baseline: 1.2661x; 1.0369x over previous
#include <cuda_runtime.h>
#include <stdint.h>

// SimpleGCN: 2-layer GCN, N=100000 nodes, C=32 channels, E=1.6M edges (int32).
// out = GCNConv2( relu( GCNConv1(x) ) ), self-loops, symmetric norm.
//
// Algebraic form used here (no per-edge norm):
//   out[i] = b + dis[i] * ( sum_{j->i} dis[j]*h[j]  +  dis[i]*h[i] )
// GEMM epilogue stores h~ = dis*h and seeds acc with h~ (self-loop term);
// scatter is pure acc[col] += h~[row]; the outer dis[i]*(...)+b scale is
// folded into the next layer's input load (L1) or a final pass (L2).
//
// Inputs: x f32[N*32], edge_index i32[2*E] (rows then cols),
//         W1 f32[32*32], b1 f32[32], W2 f32[32*32], b2 f32[32]
// Output: f32[N*32]

#define GCN_N 100000
#define GCN_C 32

__device__ float g_dis[GCN_N];                          // deg -> rsqrt(deg)
__device__ __align__(16) float g_h1[GCN_N * GCN_C];     // dis * (x @ W1)
__device__ __align__(16) float g_a1[GCN_N * GCN_C];     // layer-1 accumulator
__device__ __align__(16) float g_h2[GCN_N * GCN_C];     // dis * (relu(..) @ W2)
__device__ __align__(16) float g_a2[GCN_N * GCN_C];     // layer-2 accumulator

// ---------------------------------------------------------------------------
// Degree kernels
// ---------------------------------------------------------------------------
__global__ void k_deg_init(float* __restrict__ deg, int n) {
    int i = blockIdx.x * blockDim.x + threadIdx.x;
    if (i < n) deg[i] = 1.0f;  // self-loop contributes 1
}

__global__ void k_deg_acc(const int* __restrict__ col, float* __restrict__ deg, int E) {
    int i = (blockIdx.x * blockDim.x + threadIdx.x) * 4;
    if (i + 3 < E) {
        int4 c = *(const int4*)(col + i);
        atomicAdd(&deg[c.x], 1.0f);
        atomicAdd(&deg[c.y], 1.0f);
        atomicAdd(&deg[c.z], 1.0f);
        atomicAdd(&deg[c.w], 1.0f);
    } else {
        for (int e = i; e < E; e++) atomicAdd(&deg[col[e]], 1.0f);
    }
}

__global__ void k_dis(float* __restrict__ deg, int n) {
    int i = blockIdx.x * blockDim.x + threadIdx.x;
    if (i < n) deg[i] = rsqrtf(deg[i]);  // deg >= 1 always
}

// ---------------------------------------------------------------------------
// Register-tiled GEMM.
//   in-transform (layer 2 only): v = relu(b_in[c] + dis[n]*in[n,c])
//   raw = v @ W ;  h~ = dis[n]*raw ; store h~ to both h and acc (self-loop seed)
// Block: 256 threads, 128 nodes. Thread: 4 nodes x 4 channels register tile.
// ---------------------------------------------------------------------------
template <bool TRANSFORM_IN>
__global__ __launch_bounds__(256) void k_gemm(
    const float* __restrict__ in, const float* __restrict__ W,
    const float* __restrict__ b_in, const float* __restrict__ dis,
    float* __restrict__ h, float* __restrict__ acc_out, int n)
{
    __shared__ float xT[32][132];   // [k][node], padded stride
    __shared__ float Ws[32 * 32];   // row-major [k][c]

    const int tid = threadIdx.x;
    const int base = blockIdx.x * 128;

    ((float4*)Ws)[tid] = ((const float4*)W)[tid];

    // Stage input tile transposed: 128 nodes x 32 k
    #pragma unroll
    for (int l = 0; l < 4; l++) {
        int i = tid + l * 256;
        int node = i >> 3;          // 0..127
        int kc = (i & 7) * 4;       // 0,4,...,28
        float4 v = make_float4(0.f, 0.f, 0.f, 0.f);
        if (base + node < n) {
            v = *(const float4*)(in + (size_t)(base + node) * GCN_C + kc);
            if (TRANSFORM_IN) {
                float d = dis[base + node];
                float4 bi = *(const float4*)(b_in + kc);
                v.x = fmaxf(fmaf(d, v.x, bi.x), 0.f);
                v.y = fmaxf(fmaf(d, v.y, bi.y), 0.f);
                v.z = fmaxf(fmaf(d, v.z, bi.z), 0.f);
                v.w = fmaxf(fmaf(d, v.w, bi.w), 0.f);
            }
        }
        xT[kc + 0][node] = v.x;
        xT[kc + 1][node] = v.y;
        xT[kc + 2][node] = v.z;
        xT[kc + 3][node] = v.w;
    }
    __syncthreads();

    const int tn = (tid & 31) * 4;  // node offset within tile
    const int tc = (tid >> 5) * 4;  // channel offset

    float4 a0 = {0,0,0,0}, a1 = {0,0,0,0}, a2 = {0,0,0,0}, a3 = {0,0,0,0};
    #pragma unroll
    for (int k = 0; k < 32; k++) {
        float4 a = *(const float4*)&xT[k][tn];
        float4 w = *(const float4*)&Ws[k * 32 + tc];
        a0.x = fmaf(a.x, w.x, a0.x); a0.y = fmaf(a.x, w.y, a0.y);
        a0.z = fmaf(a.x, w.z, a0.z); a0.w = fmaf(a.x, w.w, a0.w);
        a1.x = fmaf(a.y, w.x, a1.x); a1.y = fmaf(a.y, w.y, a1.y);
        a1.z = fmaf(a.y, w.z, a1.z); a1.w = fmaf(a.y, w.w, a1.w);
        a2.x = fmaf(a.z, w.x, a2.x); a2.y = fmaf(a.z, w.y, a2.y);
        a2.z = fmaf(a.z, w.z, a2.z); a2.w = fmaf(a.z, w.w, a2.w);
        a3.x = fmaf(a.w, w.x, a3.x); a3.y = fmaf(a.w, w.y, a3.y);
        a3.z = fmaf(a.w, w.z, a3.z); a3.w = fmaf(a.w, w.w, a3.w);
    }

    float4 accs[4] = {a0, a1, a2, a3};
    #pragma unroll
    for (int i = 0; i < 4; i++) {
        int node = base + tn + i;
        if (node < n) {
            float d = dis[node];
            float4 hv = accs[i];
            hv.x *= d; hv.y *= d; hv.z *= d; hv.w *= d;
            *(float4*)(h + (size_t)node * GCN_C + tc) = hv;
            *(float4*)(acc_out + (size_t)node * GCN_C + tc) = hv;  // self-loop seed
        }
    }
}

// ---------------------------------------------------------------------------
// Edge scatter: 8 lanes per edge, one float4 vector reduction each.
//   acc[col, :] += h~[row, :]
// ---------------------------------------------------------------------------
__global__ __launch_bounds__(256) void k_scatter(
    const int* __restrict__ row, const int* __restrict__ col,
    const float* __restrict__ h, float* __restrict__ acc, int E)
{
    long long tid = (long long)blockIdx.x * blockDim.x + threadIdx.x;
    int e = (int)(tid >> 3);
    if (e >= E) return;
    int sub = (int)(tid & 7);

    int r = row[e];
    int c = col[e];

    const float4 m = __ldg((const float4*)(h + (size_t)r * GCN_C + sub * 4));
    float* p = acc + (size_t)c * GCN_C + sub * 4;
    asm volatile("red.global.add.v4.f32 [%0], {%1, %2, %3, %4};"
                 :: "l"(p), "f"(m.x), "f"(m.y), "f"(m.z), "f"(m.w)
                 : "memory");
}

// ---------------------------------------------------------------------------
// Final scale: out[i,c] = b[c] + dis[i] * acc[i,c]
// ---------------------------------------------------------------------------
__global__ __launch_bounds__(256) void k_final(
    const float* __restrict__ acc, const float* __restrict__ dis,
    const float* __restrict__ b, float* __restrict__ out, int n)
{
    int i = blockIdx.x * blockDim.x + threadIdx.x;  // one float4 per thread
    if (i >= n * 8) return;
    int node = i >> 3;
    int kc = (i & 7) * 4;
    float d = dis[node];
    float4 a = *(const float4*)(acc + (size_t)i * 4);
    float4 bi = *(const float4*)(b + kc);
    float4 o;
    o.x = fmaf(d, a.x, bi.x);
    o.y = fmaf(d, a.y, bi.y);
    o.z = fmaf(d, a.z, bi.z);
    o.w = fmaf(d, a.w, bi.w);
    *(float4*)(out + (size_t)i * 4) = o;
}

// ---------------------------------------------------------------------------
// Launch
// ---------------------------------------------------------------------------
extern "C" void kernel_launch(void* const* d_in, const int* in_sizes, int n_in,
                              void* d_out, int out_size)
{
    const float* x    = (const float*)d_in[0];
    const int*   ei   = (const int*)d_in[1];
    const float* W1   = (const float*)d_in[2];
    const float* b1   = (const float*)d_in[3];
    const float* W2   = (const float*)d_in[4];
    const float* b2   = (const float*)d_in[5];
    float*       outp = (float*)d_out;

    const int E = in_sizes[1] / 2;
    const int* rows = ei;
    const int* cols = ei + E;
    const int n = GCN_N;

    float *p_dis, *p_h1, *p_a1, *p_h2, *p_a2;
    cudaGetSymbolAddress((void**)&p_dis, g_dis);
    cudaGetSymbolAddress((void**)&p_h1,  g_h1);
    cudaGetSymbolAddress((void**)&p_a1,  g_a1);
    cudaGetSymbolAddress((void**)&p_h2,  g_h2);
    cudaGetSymbolAddress((void**)&p_a2,  g_a2);

    const int T = 256;

    // degrees -> dis
    k_deg_init<<<(n + T - 1) / T, T>>>(p_dis, n);
    k_deg_acc<<<(E / 4 + T - 1) / T, T>>>(cols, p_dis, E);
    k_dis<<<(n + T - 1) / T, T>>>(p_dis, n);

    const int gemm_grid = (n + 127) / 128;
    const int scat_grid = (int)(((long long)E * 8 + T - 1) / T);

    // layer 1: h1~ = dis*(x@W1); a1 = h1~ (seed); a1 += scatter
    k_gemm<false><<<gemm_grid, T>>>(x, W1, nullptr, p_dis, p_h1, p_a1, n);
    k_scatter<<<scat_grid, T>>>(rows, cols, p_h1, p_a1, E);

    // layer 2: input transform relu(b1 + dis*a1) folded into tile load
    k_gemm<true><<<gemm_grid, T>>>(p_a1, W2, b1, p_dis, p_h2, p_a2, n);
    k_scatter<<<scat_grid, T>>>(rows, cols, p_h2, p_a2, E);

    // out = b2 + dis * a2
    k_final<<<(n * 8 + T - 1) / T, T>>>(p_a2, p_dis, b2, outp, n);
}

// round 5
// speedup vs baseline: 1.3079x; 1.0331x over previous
#include <cuda_runtime.h>
#include <stdint.h>

// SimpleGCN: 2-layer GCN, N=100000 nodes, C=32, E=1.6M edges (int32).
// out = GCNConv2( relu( GCNConv1(x) ) ), self-loops, symmetric norm.
//
// Form: out[i] = b + dis[i] * ( sum_{j->i} dis[j]*h[j] + dis[i]*h[i] )
// GEMM epilogue stores h~ = dis*h and seeds acc with h~ (self-loop term);
// scatter is pure acc[col] += h~[row]; outer scale folded into next layer's
// input load (L1) or final pass (L2). dis computed on the fly from deg.

#define GCN_N 100000
#define GCN_C 32

__device__ float g_deg[GCN_N];                          // in-degree (+1 self)
__device__ __align__(16) float g_h1[GCN_N * GCN_C];     // dis * (x @ W1)
__device__ __align__(16) float g_a1[GCN_N * GCN_C];     // layer-1 accumulator
__device__ __align__(16) float g_h2[GCN_N * GCN_C];     // dis * (relu @ W2)
__device__ __align__(16) float g_a2[GCN_N * GCN_C];     // layer-2 accumulator

// ---------------------------------------------------------------------------
// Degree kernels
// ---------------------------------------------------------------------------
__global__ void k_deg_init(float* __restrict__ deg, int n) {
    int i = blockIdx.x * blockDim.x + threadIdx.x;
    if (i < n) deg[i] = 1.0f;  // self-loop contributes 1
}

__global__ void k_deg_acc(const int* __restrict__ col, float* __restrict__ deg, int E) {
    int i = (blockIdx.x * blockDim.x + threadIdx.x) * 4;
    if (i + 3 < E) {
        int4 c = *(const int4*)(col + i);
        atomicAdd(&deg[c.x], 1.0f);
        atomicAdd(&deg[c.y], 1.0f);
        atomicAdd(&deg[c.z], 1.0f);
        atomicAdd(&deg[c.w], 1.0f);
    } else {
        for (int e = i; e < E; e++) atomicAdd(&deg[col[e]], 1.0f);
    }
}

// ---------------------------------------------------------------------------
// Register-tiled GEMM, 256 nodes/block, thread tile 2 x (4 nodes x 4 ch).
// Shared x is stored TRANSPOSED with XOR swizzle: element (k, node) at
// xT[k][node ^ (k & 28)] -> conflict-free STS (staging) and LDS.128 (compute).
//   in-transform (layer 2): v = relu(b_in[c] + dis[n]*in[n,c])
//   h~ = dis[n] * (v @ W); stored to h and acc (self-loop seed).
// ---------------------------------------------------------------------------
template <bool TRANSFORM_IN>
__global__ __launch_bounds__(256) void k_gemm(
    const float* __restrict__ in, const float* __restrict__ W,
    const float* __restrict__ b_in, const float* __restrict__ deg,
    float* __restrict__ h, float* __restrict__ acc_out, int n)
{
    __shared__ float xT[32][256];   // [k][swizzled node]
    __shared__ float Ws[32 * 32];   // row-major [k][c]
    __shared__ float disS[256];

    const int tid = threadIdx.x;
    const int base = blockIdx.x * 256;

    ((float4*)Ws)[tid] = ((const float4*)W)[tid];

    // per-node dis into shared
    {
        int node = base + tid;
        disS[tid] = (node < n) ? rsqrtf(deg[node]) : 0.0f;
    }
    __syncthreads();  // disS ready before TRANSFORM_IN staging uses it

    // Stage input tile transposed+swizzled: 256 nodes x 32 k
    #pragma unroll
    for (int l = 0; l < 8; l++) {
        int i = tid + l * 256;
        int node = i >> 3;          // 0..255
        int kc = (i & 7) * 4;       // 0,4,...,28
        float4 v = make_float4(0.f, 0.f, 0.f, 0.f);
        if (base + node < n) {
            v = *(const float4*)(in + (size_t)(base + node) * GCN_C + kc);
            if (TRANSFORM_IN) {
                float d = disS[node];
                float4 bi = *(const float4*)(b_in + kc);
                v.x = fmaxf(fmaf(d, v.x, bi.x), 0.f);
                v.y = fmaxf(fmaf(d, v.y, bi.y), 0.f);
                v.z = fmaxf(fmaf(d, v.z, bi.z), 0.f);
                v.w = fmaxf(fmaf(d, v.w, bi.w), 0.f);
            }
        }
        int sc = node ^ kc;         // s(kc+j) == kc for j<4
        xT[kc + 0][sc] = v.x;
        xT[kc + 1][sc] = v.y;
        xT[kc + 2][sc] = v.z;
        xT[kc + 3][sc] = v.w;
    }
    __syncthreads();

    const int tn = (tid & 31) * 4;  // node group (lo); hi = tn + 128
    const int tc = (tid >> 5) * 4;  // channel group (constant per warp)

    float4 l0 = {0,0,0,0}, l1 = {0,0,0,0}, l2 = {0,0,0,0}, l3 = {0,0,0,0};
    float4 u0 = {0,0,0,0}, u1 = {0,0,0,0}, u2 = {0,0,0,0}, u3 = {0,0,0,0};

    #pragma unroll
    for (int k = 0; k < 32; k++) {
        const int s = k & 28;
        float4 a = *(const float4*)&xT[k][tn ^ s];
        float4 c = *(const float4*)&xT[k][(tn + 128) ^ s];
        float4 w = *(const float4*)&Ws[k * 32 + tc];   // warp broadcast
        l0.x = fmaf(a.x, w.x, l0.x); l0.y = fmaf(a.x, w.y, l0.y);
        l0.z = fmaf(a.x, w.z, l0.z); l0.w = fmaf(a.x, w.w, l0.w);
        l1.x = fmaf(a.y, w.x, l1.x); l1.y = fmaf(a.y, w.y, l1.y);
        l1.z = fmaf(a.y, w.z, l1.z); l1.w = fmaf(a.y, w.w, l1.w);
        l2.x = fmaf(a.z, w.x, l2.x); l2.y = fmaf(a.z, w.y, l2.y);
        l2.z = fmaf(a.z, w.z, l2.z); l2.w = fmaf(a.z, w.w, l2.w);
        l3.x = fmaf(a.w, w.x, l3.x); l3.y = fmaf(a.w, w.y, l3.y);
        l3.z = fmaf(a.w, w.z, l3.z); l3.w = fmaf(a.w, w.w, l3.w);
        u0.x = fmaf(c.x, w.x, u0.x); u0.y = fmaf(c.x, w.y, u0.y);
        u0.z = fmaf(c.x, w.z, u0.z); u0.w = fmaf(c.x, w.w, u0.w);
        u1.x = fmaf(c.y, w.x, u1.x); u1.y = fmaf(c.y, w.y, u1.y);
        u1.z = fmaf(c.y, w.z, u1.z); u1.w = fmaf(c.y, w.w, u1.w);
        u2.x = fmaf(c.z, w.x, u2.x); u2.y = fmaf(c.z, w.y, u2.y);
        u2.z = fmaf(c.z, w.z, u2.z); u2.w = fmaf(c.z, w.w, u2.w);
        u3.x = fmaf(c.w, w.x, u3.x); u3.y = fmaf(c.w, w.y, u3.y);
        u3.z = fmaf(c.w, w.z, u3.z); u3.w = fmaf(c.w, w.w, u3.w);
    }

    float4 lo[4] = {l0, l1, l2, l3};
    float4 hi[4] = {u0, u1, u2, u3};
    #pragma unroll
    for (int i = 0; i < 4; i++) {
        int ln = tn + i;
        int node = base + ln;
        if (node < n) {
            float d = disS[ln];
            float4 hv = lo[i];
            hv.x *= d; hv.y *= d; hv.z *= d; hv.w *= d;
            *(float4*)(h + (size_t)node * GCN_C + tc) = hv;
            *(float4*)(acc_out + (size_t)node * GCN_C + tc) = hv;
        }
        int un = tn + 128 + i;
        int node2 = base + un;
        if (node2 < n) {
            float d = disS[un];
            float4 hv = hi[i];
            hv.x *= d; hv.y *= d; hv.z *= d; hv.w *= d;
            *(float4*)(h + (size_t)node2 * GCN_C + tc) = hv;
            *(float4*)(acc_out + (size_t)node2 * GCN_C + tc) = hv;
        }
    }
}

// ---------------------------------------------------------------------------
// Edge scatter: 8 lanes per edge, one float4 vector reduction each.
//   acc[col, :] += h~[row, :]
// ---------------------------------------------------------------------------
__global__ __launch_bounds__(256) void k_scatter(
    const int* __restrict__ row, const int* __restrict__ col,
    const float* __restrict__ h, float* __restrict__ acc, int E)
{
    long long tid = (long long)blockIdx.x * blockDim.x + threadIdx.x;
    int e = (int)(tid >> 3);
    if (e >= E) return;
    int sub = (int)(tid & 7);

    int r = row[e];
    int c = col[e];

    const float4 m = __ldg((const float4*)(h + (size_t)r * GCN_C + sub * 4));
    float* p = acc + (size_t)c * GCN_C + sub * 4;
    asm volatile("red.global.add.v4.f32 [%0], {%1, %2, %3, %4};"
                 :: "l"(p), "f"(m.x), "f"(m.y), "f"(m.z), "f"(m.w)
                 : "memory");
}

// ---------------------------------------------------------------------------
// Final: out[i,c] = b[c] + rsqrt(deg[i]) * acc[i,c]
// ---------------------------------------------------------------------------
__global__ __launch_bounds__(256) void k_final(
    const float* __restrict__ acc, const float* __restrict__ deg,
    const float* __restrict__ b, float* __restrict__ out, int n)
{
    int i = blockIdx.x * blockDim.x + threadIdx.x;  // one float4 per thread
    if (i >= n * 8) return;
    int node = i >> 3;
    int kc = (i & 7) * 4;
    float d = rsqrtf(deg[node]);
    float4 a = *(const float4*)(acc + (size_t)i * 4);
    float4 bi = *(const float4*)(b + kc);
    float4 o;
    o.x = fmaf(d, a.x, bi.x);
    o.y = fmaf(d, a.y, bi.y);
    o.z = fmaf(d, a.z, bi.z);
    o.w = fmaf(d, a.w, bi.w);
    *(float4*)(out + (size_t)i * 4) = o;
}

// ---------------------------------------------------------------------------
// Launch
// ---------------------------------------------------------------------------
extern "C" void kernel_launch(void* const* d_in, const int* in_sizes, int n_in,
                              void* d_out, int out_size)
{
    const float* x    = (const float*)d_in[0];
    const int*   ei   = (const int*)d_in[1];
    const float* W1   = (const float*)d_in[2];
    const float* b1   = (const float*)d_in[3];
    const float* W2   = (const float*)d_in[4];
    const float* b2   = (const float*)d_in[5];
    float*       outp = (float*)d_out;

    const int E = in_sizes[1] / 2;
    const int* rows = ei;
    const int* cols = ei + E;
    const int n = GCN_N;

    float *p_deg, *p_h1, *p_a1, *p_h2, *p_a2;
    cudaGetSymbolAddress((void**)&p_deg, g_deg);
    cudaGetSymbolAddress((void**)&p_h1,  g_h1);
    cudaGetSymbolAddress((void**)&p_a1,  g_a1);
    cudaGetSymbolAddress((void**)&p_h2,  g_h2);
    cudaGetSymbolAddress((void**)&p_a2,  g_a2);

    const int T = 256;

    // degrees
    k_deg_init<<<(n + T - 1) / T, T>>>(p_deg, n);
    k_deg_acc<<<(E / 4 + T - 1) / T, T>>>(cols, p_deg, E);

    const int gemm_grid = (n + 255) / 256;
    const int scat_grid = (int)(((long long)E * 8 + T - 1) / T);

    // layer 1
    k_gemm<false><<<gemm_grid, T>>>(x, W1, nullptr, p_deg, p_h1, p_a1, n);
    k_scatter<<<scat_grid, T>>>(rows, cols, p_h1, p_a1, E);

    // layer 2 (input transform relu(b1 + dis*a1) folded into tile load)
    k_gemm<true><<<gemm_grid, T>>>(p_a1, W2, b1, p_deg, p_h2, p_a2, n);
    k_scatter<<<scat_grid, T>>>(rows, cols, p_h2, p_a2, E);

    // out = b2 + dis * a2
    k_final<<<(n * 8 + T - 1) / T, T>>>(p_a2, p_deg, b2, outp, n);
}

// round 6
// speedup vs baseline: 1.4351x; 1.0973x over previous
#include <cuda_runtime.h>
#include <stdint.h>

// SimpleGCN: 2-layer GCN, N=100000 nodes, C=32, E=1.6M edges (int32).
// out = GCNConv2( relu( GCNConv1(x) ) ), self-loops, symmetric norm.
//
// Form: out[i] = b + dis[i] * ( sum_{j->i} dis[j]*h[j] + dis[i]*h[i] )
// GEMM epilogue stores h~ = dis*h and seeds acc with h~ (self-loop term);
// scatter is pure acc[col] += h~[row]; outer scale folded into next layer's
// input load (L1) or final pass (L2). dis computed on the fly from deg.

#define GCN_N 100000
#define GCN_C 32

__device__ float g_deg[GCN_N];                          // in-degree (+1 self)
__device__ __align__(16) float g_h1[GCN_N * GCN_C];     // dis * (x @ W1)
__device__ __align__(16) float g_a1[GCN_N * GCN_C];     // layer-1 accumulator
__device__ __align__(16) float g_h2[GCN_N * GCN_C];     // dis * (relu @ W2)
__device__ __align__(16) float g_a2[GCN_N * GCN_C];     // layer-2 accumulator

// ---------------------------------------------------------------------------
// Degree kernels
// ---------------------------------------------------------------------------
__global__ void k_deg_init(float* __restrict__ deg, int n) {
    int i = blockIdx.x * blockDim.x + threadIdx.x;
    if (i < n) deg[i] = 1.0f;  // self-loop contributes 1
}

__global__ void k_deg_acc(const int* __restrict__ col, float* __restrict__ deg, int E) {
    int i = (blockIdx.x * blockDim.x + threadIdx.x) * 8;
    if (i + 7 < E) {
        int4 c0 = *(const int4*)(col + i);
        int4 c1 = *(const int4*)(col + i + 4);
        atomicAdd(&deg[c0.x], 1.0f);
        atomicAdd(&deg[c0.y], 1.0f);
        atomicAdd(&deg[c0.z], 1.0f);
        atomicAdd(&deg[c0.w], 1.0f);
        atomicAdd(&deg[c1.x], 1.0f);
        atomicAdd(&deg[c1.y], 1.0f);
        atomicAdd(&deg[c1.z], 1.0f);
        atomicAdd(&deg[c1.w], 1.0f);
    } else {
        for (int e = i; e < E; e++) atomicAdd(&deg[col[e]], 1.0f);
    }
}

// ---------------------------------------------------------------------------
// Register-tiled GEMM, 256 nodes/block, thread tile 2 x (4 nodes x 4 ch).
// Shared x stored TRANSPOSED with XOR swizzle -> conflict-free STS + LDS.128.
// ---------------------------------------------------------------------------
template <bool TRANSFORM_IN>
__global__ __launch_bounds__(256) void k_gemm(
    const float* __restrict__ in, const float* __restrict__ W,
    const float* __restrict__ b_in, const float* __restrict__ deg,
    float* __restrict__ h, float* __restrict__ acc_out, int n)
{
    __shared__ float xT[32][256];   // [k][swizzled node]
    __shared__ float Ws[32 * 32];   // row-major [k][c]
    __shared__ float disS[256];

    const int tid = threadIdx.x;
    const int base = blockIdx.x * 256;

    ((float4*)Ws)[tid] = ((const float4*)W)[tid];

    {
        int node = base + tid;
        disS[tid] = (node < n) ? rsqrtf(deg[node]) : 0.0f;
    }
    __syncthreads();

    #pragma unroll
    for (int l = 0; l < 8; l++) {
        int i = tid + l * 256;
        int node = i >> 3;          // 0..255
        int kc = (i & 7) * 4;       // 0,4,...,28
        float4 v = make_float4(0.f, 0.f, 0.f, 0.f);
        if (base + node < n) {
            v = *(const float4*)(in + (size_t)(base + node) * GCN_C + kc);
            if (TRANSFORM_IN) {
                float d = disS[node];
                float4 bi = *(const float4*)(b_in + kc);
                v.x = fmaxf(fmaf(d, v.x, bi.x), 0.f);
                v.y = fmaxf(fmaf(d, v.y, bi.y), 0.f);
                v.z = fmaxf(fmaf(d, v.z, bi.z), 0.f);
                v.w = fmaxf(fmaf(d, v.w, bi.w), 0.f);
            }
        }
        int sc = node ^ kc;
        xT[kc + 0][sc] = v.x;
        xT[kc + 1][sc] = v.y;
        xT[kc + 2][sc] = v.z;
        xT[kc + 3][sc] = v.w;
    }
    __syncthreads();

    const int tn = (tid & 31) * 4;
    const int tc = (tid >> 5) * 4;

    float4 l0 = {0,0,0,0}, l1 = {0,0,0,0}, l2 = {0,0,0,0}, l3 = {0,0,0,0};
    float4 u0 = {0,0,0,0}, u1 = {0,0,0,0}, u2 = {0,0,0,0}, u3 = {0,0,0,0};

    #pragma unroll
    for (int k = 0; k < 32; k++) {
        const int s = k & 28;
        float4 a = *(const float4*)&xT[k][tn ^ s];
        float4 c = *(const float4*)&xT[k][(tn + 128) ^ s];
        float4 w = *(const float4*)&Ws[k * 32 + tc];
        l0.x = fmaf(a.x, w.x, l0.x); l0.y = fmaf(a.x, w.y, l0.y);
        l0.z = fmaf(a.x, w.z, l0.z); l0.w = fmaf(a.x, w.w, l0.w);
        l1.x = fmaf(a.y, w.x, l1.x); l1.y = fmaf(a.y, w.y, l1.y);
        l1.z = fmaf(a.y, w.z, l1.z); l1.w = fmaf(a.y, w.w, l1.w);
        l2.x = fmaf(a.z, w.x, l2.x); l2.y = fmaf(a.z, w.y, l2.y);
        l2.z = fmaf(a.z, w.z, l2.z); l2.w = fmaf(a.z, w.w, l2.w);
        l3.x = fmaf(a.w, w.x, l3.x); l3.y = fmaf(a.w, w.y, l3.y);
        l3.z = fmaf(a.w, w.z, l3.z); l3.w = fmaf(a.w, w.w, l3.w);
        u0.x = fmaf(c.x, w.x, u0.x); u0.y = fmaf(c.x, w.y, u0.y);
        u0.z = fmaf(c.x, w.z, u0.z); u0.w = fmaf(c.x, w.w, u0.w);
        u1.x = fmaf(c.y, w.x, u1.x); u1.y = fmaf(c.y, w.y, u1.y);
        u1.z = fmaf(c.y, w.z, u1.z); u1.w = fmaf(c.y, w.w, u1.w);
        u2.x = fmaf(c.z, w.x, u2.x); u2.y = fmaf(c.z, w.y, u2.y);
        u2.z = fmaf(c.z, w.z, u2.z); u2.w = fmaf(c.z, w.w, u2.w);
        u3.x = fmaf(c.w, w.x, u3.x); u3.y = fmaf(c.w, w.y, u3.y);
        u3.z = fmaf(c.w, w.z, u3.z); u3.w = fmaf(c.w, w.w, u3.w);
    }

    float4 lo[4] = {l0, l1, l2, l3};
    float4 hi[4] = {u0, u1, u2, u3};
    #pragma unroll
    for (int i = 0; i < 4; i++) {
        int ln = tn + i;
        int node = base + ln;
        if (node < n) {
            float d = disS[ln];
            float4 hv = lo[i];
            hv.x *= d; hv.y *= d; hv.z *= d; hv.w *= d;
            *(float4*)(h + (size_t)node * GCN_C + tc) = hv;
            *(float4*)(acc_out + (size_t)node * GCN_C + tc) = hv;
        }
        int un = tn + 128 + i;
        int node2 = base + un;
        if (node2 < n) {
            float d = disS[un];
            float4 hv = hi[i];
            hv.x *= d; hv.y *= d; hv.z *= d; hv.w *= d;
            *(float4*)(h + (size_t)node2 * GCN_C + tc) = hv;
            *(float4*)(acc_out + (size_t)node2 * GCN_C + tc) = hv;
        }
    }
}

// ---------------------------------------------------------------------------
// Edge scatter, x4 unrolled: each 8-lane team handles 4 edges at quarter
// stride (e, e+Q, e+2Q, e+3Q). All index loads then all gathers issued
// before any RED -> per-thread MLP=4+, hides L2 latency.
//   acc[col, :] += h~[row, :]
// ---------------------------------------------------------------------------
__global__ __launch_bounds__(256) void k_scatter4(
    const int* __restrict__ row, const int* __restrict__ col,
    const float* __restrict__ h, float* __restrict__ acc, int E)
{
    const int Q = (E + 3) >> 2;   // quarter size (teams per quarter)
    long long tid = (long long)blockIdx.x * blockDim.x + threadIdx.x;
    int team = (int)(tid >> 3);
    if (team >= Q) return;
    int sub = (int)(tid & 7);
    const int off = sub * 4;

    int e0 = team;
    int e1 = team + Q;
    int e2 = team + 2 * Q;
    int e3 = team + 3 * Q;
    bool p1 = e1 < E, p2 = e2 < E, p3 = e3 < E;  // e0 always valid (Q<=E)

    // batch index loads
    int r0 = row[e0], c0 = col[e0];
    int r1 = p1 ? row[e1] : 0, c1 = p1 ? col[e1] : 0;
    int r2 = p2 ? row[e2] : 0, c2 = p2 ? col[e2] : 0;
    int r3 = p3 ? row[e3] : 0, c3 = p3 ? col[e3] : 0;

    // batch gathers (independent)
    float4 m0 = __ldg((const float4*)(h + (size_t)r0 * GCN_C + off));
    float4 m1 = p1 ? __ldg((const float4*)(h + (size_t)r1 * GCN_C + off)) : make_float4(0,0,0,0);
    float4 m2 = p2 ? __ldg((const float4*)(h + (size_t)r2 * GCN_C + off)) : make_float4(0,0,0,0);
    float4 m3 = p3 ? __ldg((const float4*)(h + (size_t)r3 * GCN_C + off)) : make_float4(0,0,0,0);

    float* q0 = acc + (size_t)c0 * GCN_C + off;
    asm volatile("red.global.add.v4.f32 [%0], {%1, %2, %3, %4};"
                 :: "l"(q0), "f"(m0.x), "f"(m0.y), "f"(m0.z), "f"(m0.w) : "memory");
    if (p1) {
        float* q1 = acc + (size_t)c1 * GCN_C + off;
        asm volatile("red.global.add.v4.f32 [%0], {%1, %2, %3, %4};"
                     :: "l"(q1), "f"(m1.x), "f"(m1.y), "f"(m1.z), "f"(m1.w) : "memory");
    }
    if (p2) {
        float* q2 = acc + (size_t)c2 * GCN_C + off;
        asm volatile("red.global.add.v4.f32 [%0], {%1, %2, %3, %4};"
                     :: "l"(q2), "f"(m2.x), "f"(m2.y), "f"(m2.z), "f"(m2.w) : "memory");
    }
    if (p3) {
        float* q3 = acc + (size_t)c3 * GCN_C + off;
        asm volatile("red.global.add.v4.f32 [%0], {%1, %2, %3, %4};"
                     :: "l"(q3), "f"(m3.x), "f"(m3.y), "f"(m3.z), "f"(m3.w) : "memory");
    }
}

// ---------------------------------------------------------------------------
// Final: out[i,c] = b[c] + rsqrt(deg[i]) * acc[i,c]
// ---------------------------------------------------------------------------
__global__ __launch_bounds__(256) void k_final(
    const float* __restrict__ acc, const float* __restrict__ deg,
    const float* __restrict__ b, float* __restrict__ out, int n)
{
    int i = blockIdx.x * blockDim.x + threadIdx.x;  // one float4 per thread
    if (i >= n * 8) return;
    int node = i >> 3;
    int kc = (i & 7) * 4;
    float d = rsqrtf(deg[node]);
    float4 a = *(const float4*)(acc + (size_t)i * 4);
    float4 bi = *(const float4*)(b + kc);
    float4 o;
    o.x = fmaf(d, a.x, bi.x);
    o.y = fmaf(d, a.y, bi.y);
    o.z = fmaf(d, a.z, bi.z);
    o.w = fmaf(d, a.w, bi.w);
    *(float4*)(out + (size_t)i * 4) = o;
}

// ---------------------------------------------------------------------------
// Launch
// ---------------------------------------------------------------------------
extern "C" void kernel_launch(void* const* d_in, const int* in_sizes, int n_in,
                              void* d_out, int out_size)
{
    const float* x    = (const float*)d_in[0];
    const int*   ei   = (const int*)d_in[1];
    const float* W1   = (const float*)d_in[2];
    const float* b1   = (const float*)d_in[3];
    const float* W2   = (const float*)d_in[4];
    const float* b2   = (const float*)d_in[5];
    float*       outp = (float*)d_out;

    const int E = in_sizes[1] / 2;
    const int* rows = ei;
    const int* cols = ei + E;
    const int n = GCN_N;

    float *p_deg, *p_h1, *p_a1, *p_h2, *p_a2;
    cudaGetSymbolAddress((void**)&p_deg, g_deg);
    cudaGetSymbolAddress((void**)&p_h1,  g_h1);
    cudaGetSymbolAddress((void**)&p_a1,  g_a1);
    cudaGetSymbolAddress((void**)&p_h2,  g_h2);
    cudaGetSymbolAddress((void**)&p_a2,  g_a2);

    const int T = 256;

    // degrees
    k_deg_init<<<(n + T - 1) / T, T>>>(p_deg, n);
    k_deg_acc<<<(E / 8 + T - 1) / T, T>>>(cols, p_deg, E);

    const int gemm_grid = (n + 255) / 256;
    const int Q = (E + 3) >> 2;
    const int scat_grid = (int)(((long long)Q * 8 + T - 1) / T);

    // layer 1
    k_gemm<false><<<gemm_grid, T>>>(x, W1, nullptr, p_deg, p_h1, p_a1, n);
    k_scatter4<<<scat_grid, T>>>(rows, cols, p_h1, p_a1, E);

    // layer 2 (input transform relu(b1 + dis*a1) folded into tile load)
    k_gemm<true><<<gemm_grid, T>>>(p_a1, W2, b1, p_deg, p_h2, p_a2, n);
    k_scatter4<<<scat_grid, T>>>(rows, cols, p_h2, p_a2, E);

    // out = b2 + dis * a2
    k_final<<<(n * 8 + T - 1) / T, T>>>(p_a2, p_deg, b2, outp, n);
}

// round 7
// speedup vs baseline: 1.6486x; 1.1488x over previous
#include <cuda_runtime.h>
#include <stdint.h>

// SimpleGCN: 2-layer GCN, N=100000 nodes, C=32, E=1.6M edges (int32).
// out = GCNConv2( relu( GCNConv1(x) ) ), self-loops, symmetric norm.
//
// Pull-mode CSR formulation (no feature atomics):
//   h~ = dis * (in @ W)            (dense GEMM, dis[i]=rsqrt(1+indeg[i]))
//   t[i] = act( b + dis[i] * ( h~[i] + sum_{(j->i)} h~[j] ) )
// CSR (rowptr/adj by destination) built per launch via histogram+scan+cursor.

#define GCN_N 100000
#define GCN_C 32
#define GCN_EMAX 1600000
#define SCAN_B 1024

__device__ int g_cnt[GCN_N];            // in-degree (excl self)
__device__ int g_rowptr[GCN_N + 1];
__device__ int g_cursor[GCN_N];
__device__ int g_adj[GCN_EMAX];         // source node per incoming edge
__device__ int g_bsum[128];             // scan block sums (nb <= 128)
__device__ float g_dis[GCN_N];
__device__ __align__(16) float g_h[GCN_N * GCN_C];   // dis * (in @ W)
__device__ __align__(16) float g_t[GCN_N * GCN_C];   // layer-1 activations

// ---------------------------------------------------------------------------
// CSR build
// ---------------------------------------------------------------------------
__global__ void k_cnt_init(int* __restrict__ cnt, int n) {
    int i = blockIdx.x * blockDim.x + threadIdx.x;
    if (i < n) cnt[i] = 0;
}

__global__ void k_cnt_acc(const int* __restrict__ col, int* __restrict__ cnt, int E) {
    int i = (blockIdx.x * blockDim.x + threadIdx.x) * 8;
    if (i + 7 < E) {
        int4 c0 = *(const int4*)(col + i);
        int4 c1 = *(const int4*)(col + i + 4);
        atomicAdd(&cnt[c0.x], 1); atomicAdd(&cnt[c0.y], 1);
        atomicAdd(&cnt[c0.z], 1); atomicAdd(&cnt[c0.w], 1);
        atomicAdd(&cnt[c1.x], 1); atomicAdd(&cnt[c1.y], 1);
        atomicAdd(&cnt[c1.z], 1); atomicAdd(&cnt[c1.w], 1);
    } else {
        for (int e = i; e < E; e++) atomicAdd(&cnt[col[e]], 1);
    }
}

__global__ __launch_bounds__(SCAN_B) void k_scan_block(
    const int* __restrict__ cnt, int* __restrict__ rowptr, int* __restrict__ bsum, int n)
{
    __shared__ int s[SCAN_B];
    int tid = threadIdx.x;
    int i = blockIdx.x * SCAN_B + tid;
    int v = (i < n) ? cnt[i] : 0;
    s[tid] = v;
    __syncthreads();
    #pragma unroll
    for (int off = 1; off < SCAN_B; off <<= 1) {
        int t = (tid >= off) ? s[tid - off] : 0;
        __syncthreads();
        s[tid] += t;
        __syncthreads();
    }
    if (i < n) rowptr[i] = s[tid] - v;            // exclusive within block
    if (tid == SCAN_B - 1) bsum[blockIdx.x] = s[tid];
}

__global__ void k_scan_bsum(int* __restrict__ bsum, int nb) {
    __shared__ int s[128];
    int tid = threadIdx.x;
    int v = (tid < nb) ? bsum[tid] : 0;
    s[tid] = v;
    __syncthreads();
    #pragma unroll
    for (int off = 1; off < 128; off <<= 1) {
        int t = (tid >= off) ? s[tid - off] : 0;
        __syncthreads();
        s[tid] += t;
        __syncthreads();
    }
    if (tid < nb) bsum[tid] = s[tid] - v;          // exclusive block offsets
}

__global__ __launch_bounds__(SCAN_B) void k_scan_add(
    int* __restrict__ rowptr, int* __restrict__ cursor,
    const int* __restrict__ bsum, int n, int E)
{
    int i = blockIdx.x * SCAN_B + threadIdx.x;
    if (i < n) {
        int v = rowptr[i] + bsum[blockIdx.x];
        rowptr[i] = v;
        cursor[i] = v;
    }
    if (i == 0) rowptr[n] = E;
}

__global__ void k_build(const int* __restrict__ row, const int* __restrict__ col,
                        int* __restrict__ cursor, int* __restrict__ adj, int E)
{
    int i = (blockIdx.x * blockDim.x + threadIdx.x) * 4;
    if (i + 3 < E) {
        int4 c = *(const int4*)(col + i);
        int4 r = *(const int4*)(row + i);
        adj[atomicAdd(&cursor[c.x], 1)] = r.x;
        adj[atomicAdd(&cursor[c.y], 1)] = r.y;
        adj[atomicAdd(&cursor[c.z], 1)] = r.z;
        adj[atomicAdd(&cursor[c.w], 1)] = r.w;
    } else {
        for (int e = i; e < E; e++)
            adj[atomicAdd(&cursor[col[e]], 1)] = row[e];
    }
}

__global__ void k_dis(const int* __restrict__ rowptr, float* __restrict__ dis, int n) {
    int i = blockIdx.x * blockDim.x + threadIdx.x;
    if (i < n) dis[i] = rsqrtf((float)(1 + rowptr[i + 1] - rowptr[i]));
}

// ---------------------------------------------------------------------------
// Register-tiled GEMM: h~ = dis * (in @ W).
// 256 nodes/block, thread tile 2 x (4 nodes x 4 ch), XOR-swizzled shared.
// ---------------------------------------------------------------------------
__global__ __launch_bounds__(256) void k_gemm(
    const float* __restrict__ in, const float* __restrict__ W,
    const float* __restrict__ dis, float* __restrict__ h, int n)
{
    __shared__ float xT[32][256];   // [k][swizzled node]
    __shared__ float Ws[32 * 32];   // row-major [k][c]
    __shared__ float disS[256];

    const int tid = threadIdx.x;
    const int base = blockIdx.x * 256;

    ((float4*)Ws)[tid] = ((const float4*)W)[tid];
    {
        int node = base + tid;
        disS[tid] = (node < n) ? dis[node] : 0.0f;
    }

    #pragma unroll
    for (int l = 0; l < 8; l++) {
        int i = tid + l * 256;
        int node = i >> 3;          // 0..255
        int kc = (i & 7) * 4;       // 0,4,...,28
        float4 v = make_float4(0.f, 0.f, 0.f, 0.f);
        if (base + node < n)
            v = *(const float4*)(in + (size_t)(base + node) * GCN_C + kc);
        int sc = node ^ kc;
        xT[kc + 0][sc] = v.x;
        xT[kc + 1][sc] = v.y;
        xT[kc + 2][sc] = v.z;
        xT[kc + 3][sc] = v.w;
    }
    __syncthreads();

    const int tn = (tid & 31) * 4;
    const int tc = (tid >> 5) * 4;

    float4 l0 = {0,0,0,0}, l1 = {0,0,0,0}, l2 = {0,0,0,0}, l3 = {0,0,0,0};
    float4 u0 = {0,0,0,0}, u1 = {0,0,0,0}, u2 = {0,0,0,0}, u3 = {0,0,0,0};

    #pragma unroll
    for (int k = 0; k < 32; k++) {
        const int s = k & 28;
        float4 a = *(const float4*)&xT[k][tn ^ s];
        float4 c = *(const float4*)&xT[k][(tn + 128) ^ s];
        float4 w = *(const float4*)&Ws[k * 32 + tc];
        l0.x = fmaf(a.x, w.x, l0.x); l0.y = fmaf(a.x, w.y, l0.y);
        l0.z = fmaf(a.x, w.z, l0.z); l0.w = fmaf(a.x, w.w, l0.w);
        l1.x = fmaf(a.y, w.x, l1.x); l1.y = fmaf(a.y, w.y, l1.y);
        l1.z = fmaf(a.y, w.z, l1.z); l1.w = fmaf(a.y, w.w, l1.w);
        l2.x = fmaf(a.z, w.x, l2.x); l2.y = fmaf(a.z, w.y, l2.y);
        l2.z = fmaf(a.z, w.z, l2.z); l2.w = fmaf(a.z, w.w, l2.w);
        l3.x = fmaf(a.w, w.x, l3.x); l3.y = fmaf(a.w, w.y, l3.y);
        l3.z = fmaf(a.w, w.z, l3.z); l3.w = fmaf(a.w, w.w, l3.w);
        u0.x = fmaf(c.x, w.x, u0.x); u0.y = fmaf(c.x, w.y, u0.y);
        u0.z = fmaf(c.x, w.z, u0.z); u0.w = fmaf(c.x, w.w, u0.w);
        u1.x = fmaf(c.y, w.x, u1.x); u1.y = fmaf(c.y, w.y, u1.y);
        u1.z = fmaf(c.y, w.z, u1.z); u1.w = fmaf(c.y, w.w, u1.w);
        u2.x = fmaf(c.z, w.x, u2.x); u2.y = fmaf(c.z, w.y, u2.y);
        u2.z = fmaf(c.z, w.z, u2.z); u2.w = fmaf(c.z, w.w, u2.w);
        u3.x = fmaf(c.w, w.x, u3.x); u3.y = fmaf(c.w, w.y, u3.y);
        u3.z = fmaf(c.w, w.z, u3.z); u3.w = fmaf(c.w, w.w, u3.w);
    }

    float4 lo[4] = {l0, l1, l2, l3};
    float4 hi[4] = {u0, u1, u2, u3};
    #pragma unroll
    for (int i = 0; i < 4; i++) {
        int ln = tn + i;
        int node = base + ln;
        if (node < n) {
            float d = disS[ln];
            float4 hv = lo[i];
            hv.x *= d; hv.y *= d; hv.z *= d; hv.w *= d;
            *(float4*)(h + (size_t)node * GCN_C + tc) = hv;
        }
        int un = tn + 128 + i;
        int node2 = base + un;
        if (node2 < n) {
            float d = disS[un];
            float4 hv = hi[i];
            hv.x *= d; hv.y *= d; hv.z *= d; hv.w *= d;
            *(float4*)(h + (size_t)node2 * GCN_C + tc) = hv;
        }
    }
}

// ---------------------------------------------------------------------------
// Pull-mode aggregation: 8-lane team per destination node.
//   acc = h~[i] + sum_{src in adj[rowptr[i]..rowptr[i+1])} h~[src]
//   out = (RELU? relu : id)( b[c] + dis[i] * acc )
// x4-unrolled independent gathers -> MLP 4/thread.
// ---------------------------------------------------------------------------
template <bool RELU>
__global__ __launch_bounds__(256) void k_gather(
    const int* __restrict__ rowptr, const int* __restrict__ adj,
    const float* __restrict__ h, const float* __restrict__ dis,
    const float* __restrict__ b, float* __restrict__ out, int n)
{
    long long tid = (long long)blockIdx.x * blockDim.x + threadIdx.x;
    int node = (int)(tid >> 3);
    if (node >= n) return;
    const int off = (int)(tid & 7) * 4;

    int j   = rowptr[node];
    int end = rowptr[node + 1];
    float d = dis[node];

    float4 acc = *(const float4*)(h + (size_t)node * GCN_C + off);  // self-loop

    for (; j + 4 <= end; j += 4) {
        int s0 = adj[j], s1 = adj[j + 1], s2 = adj[j + 2], s3 = adj[j + 3];
        float4 m0 = __ldg((const float4*)(h + (size_t)s0 * GCN_C + off));
        float4 m1 = __ldg((const float4*)(h + (size_t)s1 * GCN_C + off));
        float4 m2 = __ldg((const float4*)(h + (size_t)s2 * GCN_C + off));
        float4 m3 = __ldg((const float4*)(h + (size_t)s3 * GCN_C + off));
        acc.x += (m0.x + m1.x) + (m2.x + m3.x);
        acc.y += (m0.y + m1.y) + (m2.y + m3.y);
        acc.z += (m0.z + m1.z) + (m2.z + m3.z);
        acc.w += (m0.w + m1.w) + (m2.w + m3.w);
    }
    for (; j < end; j++) {
        int s = adj[j];
        float4 m = __ldg((const float4*)(h + (size_t)s * GCN_C + off));
        acc.x += m.x; acc.y += m.y; acc.z += m.z; acc.w += m.w;
    }

    float4 bi = __ldg((const float4*)(b + off));
    float4 o;
    o.x = fmaf(d, acc.x, bi.x);
    o.y = fmaf(d, acc.y, bi.y);
    o.z = fmaf(d, acc.z, bi.z);
    o.w = fmaf(d, acc.w, bi.w);
    if (RELU) {
        o.x = fmaxf(o.x, 0.f); o.y = fmaxf(o.y, 0.f);
        o.z = fmaxf(o.z, 0.f); o.w = fmaxf(o.w, 0.f);
    }
    *(float4*)(out + (size_t)node * GCN_C + off) = o;
}

// ---------------------------------------------------------------------------
// Launch
// ---------------------------------------------------------------------------
extern "C" void kernel_launch(void* const* d_in, const int* in_sizes, int n_in,
                              void* d_out, int out_size)
{
    const float* x    = (const float*)d_in[0];
    const int*   ei   = (const int*)d_in[1];
    const float* W1   = (const float*)d_in[2];
    const float* b1   = (const float*)d_in[3];
    const float* W2   = (const float*)d_in[4];
    const float* b2   = (const float*)d_in[5];
    float*       outp = (float*)d_out;

    const int E = in_sizes[1] / 2;
    const int* rows = ei;
    const int* cols = ei + E;
    const int n = GCN_N;

    int *p_cnt, *p_rowptr, *p_cursor, *p_adj, *p_bsum;
    float *p_dis, *p_h, *p_t;
    cudaGetSymbolAddress((void**)&p_cnt,    g_cnt);
    cudaGetSymbolAddress((void**)&p_rowptr, g_rowptr);
    cudaGetSymbolAddress((void**)&p_cursor, g_cursor);
    cudaGetSymbolAddress((void**)&p_adj,    g_adj);
    cudaGetSymbolAddress((void**)&p_bsum,   g_bsum);
    cudaGetSymbolAddress((void**)&p_dis,    g_dis);
    cudaGetSymbolAddress((void**)&p_h,      g_h);
    cudaGetSymbolAddress((void**)&p_t,      g_t);

    const int T = 256;
    const int nb = (n + SCAN_B - 1) / SCAN_B;   // 98 <= 128

    // ---- CSR build ----
    k_cnt_init<<<(n + T - 1) / T, T>>>(p_cnt, n);
    k_cnt_acc<<<(E / 8 + T - 1) / T, T>>>(cols, p_cnt, E);
    k_scan_block<<<nb, SCAN_B>>>(p_cnt, p_rowptr, p_bsum, n);
    k_scan_bsum<<<1, 128>>>(p_bsum, nb);
    k_scan_add<<<nb, SCAN_B>>>(p_rowptr, p_cursor, p_bsum, n, E);
    k_build<<<(E / 4 + T - 1) / T, T>>>(rows, cols, p_cursor, p_adj, E);
    k_dis<<<(n + T - 1) / T, T>>>(p_rowptr, p_dis, n);

    const int gemm_grid = (n + 255) / 256;
    const int gath_grid = (int)(((long long)n * 8 + T - 1) / T);

    // ---- layer 1 ----
    k_gemm<<<gemm_grid, T>>>(x, W1, p_dis, p_h, n);
    k_gather<true><<<gath_grid, T>>>(p_rowptr, p_adj, p_h, p_dis, b1, p_t, n);

    // ---- layer 2 ----
    k_gemm<<<gemm_grid, T>>>(p_t, W2, p_dis, p_h, n);
    k_gather<false><<<gath_grid, T>>>(p_rowptr, p_adj, p_h, p_dis, b2, outp, n);
}

// round 8
// speedup vs baseline: 1.8930x; 1.1482x over previous
#include <cuda_runtime.h>
#include <stdint.h>

// SimpleGCN: 2-layer GCN, N=100000 nodes, C=32, E=1.6M edges (int32).
// out = GCNConv2( relu( GCNConv1(x) ) ), self-loops, symmetric norm.
//
// Pull-mode CSR formulation (no feature atomics):
//   h~ = dis * (in @ W)            (dense GEMM, dis[i]=rsqrt(1+indeg[i]))
//   t[i] = act( b + dis[i] * ( h~[i] + sum_{(j->i)} h~[j] ) )
// CSR (start/cnt/adj by destination) built per launch:
//   zero -> histogram -> single-kernel scan (shuffle scan + atomic block base,
//   also emits dis) -> cursor fill. 8 launches total.

#define GCN_N 100000
#define GCN_C 32
#define GCN_EMAX 1600000

__device__ int g_cnt[GCN_N];            // in-degree (excl self)
__device__ int g_start[GCN_N];          // CSR start offset per node
__device__ int g_cursor[GCN_N];
__device__ int g_adj[GCN_EMAX];         // source node per incoming edge
__device__ int g_ctr;                   // global offset counter
__device__ float g_dis[GCN_N];
__device__ __align__(16) float g_h[GCN_N * GCN_C];   // dis * (in @ W)
__device__ __align__(16) float g_t[GCN_N * GCN_C];   // layer-1 activations

// ---------------------------------------------------------------------------
// CSR build
// ---------------------------------------------------------------------------
__global__ void k_zero(int* __restrict__ cnt, int* __restrict__ ctr, int n) {
    int i = blockIdx.x * blockDim.x + threadIdx.x;
    if (i < n) cnt[i] = 0;
    if (i == 0) *ctr = 0;
}

__global__ void k_hist(const int* __restrict__ col, int* __restrict__ cnt, int E) {
    int i = (blockIdx.x * blockDim.x + threadIdx.x) * 8;
    if (i + 7 < E) {
        int4 c0 = *(const int4*)(col + i);
        int4 c1 = *(const int4*)(col + i + 4);
        atomicAdd(&cnt[c0.x], 1); atomicAdd(&cnt[c0.y], 1);
        atomicAdd(&cnt[c0.z], 1); atomicAdd(&cnt[c0.w], 1);
        atomicAdd(&cnt[c1.x], 1); atomicAdd(&cnt[c1.y], 1);
        atomicAdd(&cnt[c1.z], 1); atomicAdd(&cnt[c1.w], 1);
    } else {
        for (int e = i; e < E; e++) atomicAdd(&cnt[col[e]], 1);
    }
}

// Single-kernel scan: per-block shuffle scan, block base via atomicAdd.
// Block bases depend on run order -> start[] layout varies per launch, but
// (start, cnt) is always a valid CSR partition. Also emits dis.
__global__ __launch_bounds__(1024) void k_offset(
    const int* __restrict__ cnt, int* __restrict__ start, int* __restrict__ cursor,
    float* __restrict__ dis, int* __restrict__ ctr, int n)
{
    __shared__ int warp_tot[32];
    __shared__ int block_base;
    const int tid = threadIdx.x;
    const int lane = tid & 31;
    const int wid = tid >> 5;
    const int i = blockIdx.x * 1024 + tid;
    const int v = (i < n) ? cnt[i] : 0;

    // warp inclusive scan
    int x = v;
    #pragma unroll
    for (int o = 1; o < 32; o <<= 1) {
        int t = __shfl_up_sync(0xffffffffu, x, o);
        if (lane >= o) x += t;
    }
    if (lane == 31) warp_tot[wid] = x;
    __syncthreads();
    if (wid == 0) {
        int w = warp_tot[lane];
        #pragma unroll
        for (int o = 1; o < 32; o <<= 1) {
            int t = __shfl_up_sync(0xffffffffu, w, o);
            if (lane >= o) w += t;
        }
        warp_tot[lane] = w;   // inclusive prefix of warp totals
        if (lane == 31) block_base = atomicAdd(ctr, w);
    }
    __syncthreads();

    if (i < n) {
        int woff = (wid > 0) ? warp_tot[wid - 1] : 0;
        int excl = block_base + woff + (x - v);
        start[i] = excl;
        cursor[i] = excl;
        dis[i] = rsqrtf((float)(1 + v));
    }
}

__global__ void k_build(const int* __restrict__ row, const int* __restrict__ col,
                        int* __restrict__ cursor, int* __restrict__ adj, int E)
{
    int i = (blockIdx.x * blockDim.x + threadIdx.x) * 4;
    if (i + 3 < E) {
        int4 c = *(const int4*)(col + i);
        int4 r = *(const int4*)(row + i);
        adj[atomicAdd(&cursor[c.x], 1)] = r.x;
        adj[atomicAdd(&cursor[c.y], 1)] = r.y;
        adj[atomicAdd(&cursor[c.z], 1)] = r.z;
        adj[atomicAdd(&cursor[c.w], 1)] = r.w;
    } else {
        for (int e = i; e < E; e++)
            adj[atomicAdd(&cursor[col[e]], 1)] = row[e];
    }
}

// ---------------------------------------------------------------------------
// Register-tiled GEMM: h~ = dis * (in @ W).
// 256 nodes/block, thread tile 2 x (4 nodes x 4 ch), XOR-swizzled shared.
// ---------------------------------------------------------------------------
__global__ __launch_bounds__(256) void k_gemm(
    const float* __restrict__ in, const float* __restrict__ W,
    const float* __restrict__ dis, float* __restrict__ h, int n)
{
    __shared__ float xT[32][256];   // [k][swizzled node]
    __shared__ float Ws[32 * 32];   // row-major [k][c]
    __shared__ float disS[256];

    const int tid = threadIdx.x;
    const int base = blockIdx.x * 256;

    ((float4*)Ws)[tid] = ((const float4*)W)[tid];
    {
        int node = base + tid;
        disS[tid] = (node < n) ? dis[node] : 0.0f;
    }

    #pragma unroll
    for (int l = 0; l < 8; l++) {
        int i = tid + l * 256;
        int node = i >> 3;          // 0..255
        int kc = (i & 7) * 4;       // 0,4,...,28
        float4 v = make_float4(0.f, 0.f, 0.f, 0.f);
        if (base + node < n)
            v = *(const float4*)(in + (size_t)(base + node) * GCN_C + kc);
        int sc = node ^ kc;
        xT[kc + 0][sc] = v.x;
        xT[kc + 1][sc] = v.y;
        xT[kc + 2][sc] = v.z;
        xT[kc + 3][sc] = v.w;
    }
    __syncthreads();

    const int tn = (tid & 31) * 4;
    const int tc = (tid >> 5) * 4;

    float4 l0 = {0,0,0,0}, l1 = {0,0,0,0}, l2 = {0,0,0,0}, l3 = {0,0,0,0};
    float4 u0 = {0,0,0,0}, u1 = {0,0,0,0}, u2 = {0,0,0,0}, u3 = {0,0,0,0};

    #pragma unroll
    for (int k = 0; k < 32; k++) {
        const int s = k & 28;
        float4 a = *(const float4*)&xT[k][tn ^ s];
        float4 c = *(const float4*)&xT[k][(tn + 128) ^ s];
        float4 w = *(const float4*)&Ws[k * 32 + tc];
        l0.x = fmaf(a.x, w.x, l0.x); l0.y = fmaf(a.x, w.y, l0.y);
        l0.z = fmaf(a.x, w.z, l0.z); l0.w = fmaf(a.x, w.w, l0.w);
        l1.x = fmaf(a.y, w.x, l1.x); l1.y = fmaf(a.y, w.y, l1.y);
        l1.z = fmaf(a.y, w.z, l1.z); l1.w = fmaf(a.y, w.w, l1.w);
        l2.x = fmaf(a.z, w.x, l2.x); l2.y = fmaf(a.z, w.y, l2.y);
        l2.z = fmaf(a.z, w.z, l2.z); l2.w = fmaf(a.z, w.w, l2.w);
        l3.x = fmaf(a.w, w.x, l3.x); l3.y = fmaf(a.w, w.y, l3.y);
        l3.z = fmaf(a.w, w.z, l3.z); l3.w = fmaf(a.w, w.w, l3.w);
        u0.x = fmaf(c.x, w.x, u0.x); u0.y = fmaf(c.x, w.y, u0.y);
        u0.z = fmaf(c.x, w.z, u0.z); u0.w = fmaf(c.x, w.w, u0.w);
        u1.x = fmaf(c.y, w.x, u1.x); u1.y = fmaf(c.y, w.y, u1.y);
        u1.z = fmaf(c.y, w.z, u1.z); u1.w = fmaf(c.y, w.w, u1.w);
        u2.x = fmaf(c.z, w.x, u2.x); u2.y = fmaf(c.z, w.y, u2.y);
        u2.z = fmaf(c.z, w.z, u2.z); u2.w = fmaf(c.z, w.w, u2.w);
        u3.x = fmaf(c.w, w.x, u3.x); u3.y = fmaf(c.w, w.y, u3.y);
        u3.z = fmaf(c.w, w.z, u3.z); u3.w = fmaf(c.w, w.w, u3.w);
    }

    float4 lo[4] = {l0, l1, l2, l3};
    float4 hi[4] = {u0, u1, u2, u3};
    #pragma unroll
    for (int i = 0; i < 4; i++) {
        int ln = tn + i;
        int node = base + ln;
        if (node < n) {
            float d = disS[ln];
            float4 hv = lo[i];
            hv.x *= d; hv.y *= d; hv.z *= d; hv.w *= d;
            *(float4*)(h + (size_t)node * GCN_C + tc) = hv;
        }
        int un = tn + 128 + i;
        int node2 = base + un;
        if (node2 < n) {
            float d = disS[un];
            float4 hv = hi[i];
            hv.x *= d; hv.y *= d; hv.z *= d; hv.w *= d;
            *(float4*)(h + (size_t)node2 * GCN_C + tc) = hv;
        }
    }
}

// ---------------------------------------------------------------------------
// Pull-mode aggregation: 8-lane team per destination node.
//   acc = h~[i] + sum_{src in adj[start[i] .. start[i]+cnt[i])} h~[src]
//   out = (RELU? relu : id)( b[c] + dis[i] * acc )
// x4-unrolled independent gathers -> MLP 4/thread.
// ---------------------------------------------------------------------------
template <bool RELU>
__global__ __launch_bounds__(256) void k_gather(
    const int* __restrict__ start, const int* __restrict__ cnt,
    const int* __restrict__ adj,
    const float* __restrict__ h, const float* __restrict__ dis,
    const float* __restrict__ b, float* __restrict__ out, int n)
{
    long long tid = (long long)blockIdx.x * blockDim.x + threadIdx.x;
    int node = (int)(tid >> 3);
    if (node >= n) return;
    const int off = (int)(tid & 7) * 4;

    int j   = start[node];
    int end = j + cnt[node];
    float d = dis[node];

    float4 acc = *(const float4*)(h + (size_t)node * GCN_C + off);  // self-loop

    for (; j + 4 <= end; j += 4) {
        int s0 = adj[j], s1 = adj[j + 1], s2 = adj[j + 2], s3 = adj[j + 3];
        float4 m0 = __ldg((const float4*)(h + (size_t)s0 * GCN_C + off));
        float4 m1 = __ldg((const float4*)(h + (size_t)s1 * GCN_C + off));
        float4 m2 = __ldg((const float4*)(h + (size_t)s2 * GCN_C + off));
        float4 m3 = __ldg((const float4*)(h + (size_t)s3 * GCN_C + off));
        acc.x += (m0.x + m1.x) + (m2.x + m3.x);
        acc.y += (m0.y + m1.y) + (m2.y + m3.y);
        acc.z += (m0.z + m1.z) + (m2.z + m3.z);
        acc.w += (m0.w + m1.w) + (m2.w + m3.w);
    }
    for (; j < end; j++) {
        int s = adj[j];
        float4 m = __ldg((const float4*)(h + (size_t)s * GCN_C + off));
        acc.x += m.x; acc.y += m.y; acc.z += m.z; acc.w += m.w;
    }

    float4 bi = __ldg((const float4*)(b + off));
    float4 o;
    o.x = fmaf(d, acc.x, bi.x);
    o.y = fmaf(d, acc.y, bi.y);
    o.z = fmaf(d, acc.z, bi.z);
    o.w = fmaf(d, acc.w, bi.w);
    if (RELU) {
        o.x = fmaxf(o.x, 0.f); o.y = fmaxf(o.y, 0.f);
        o.z = fmaxf(o.z, 0.f); o.w = fmaxf(o.w, 0.f);
    }
    *(float4*)(out + (size_t)node * GCN_C + off) = o;
}

// ---------------------------------------------------------------------------
// Launch
// ---------------------------------------------------------------------------
extern "C" void kernel_launch(void* const* d_in, const int* in_sizes, int n_in,
                              void* d_out, int out_size)
{
    const float* x    = (const float*)d_in[0];
    const int*   ei   = (const int*)d_in[1];
    const float* W1   = (const float*)d_in[2];
    const float* b1   = (const float*)d_in[3];
    const float* W2   = (const float*)d_in[4];
    const float* b2   = (const float*)d_in[5];
    float*       outp = (float*)d_out;

    const int E = in_sizes[1] / 2;
    const int* rows = ei;
    const int* cols = ei + E;
    const int n = GCN_N;

    int *p_cnt, *p_start, *p_cursor, *p_adj, *p_ctr;
    float *p_dis, *p_h, *p_t;
    cudaGetSymbolAddress((void**)&p_cnt,    g_cnt);
    cudaGetSymbolAddress((void**)&p_start,  g_start);
    cudaGetSymbolAddress((void**)&p_cursor, g_cursor);
    cudaGetSymbolAddress((void**)&p_adj,    g_adj);
    cudaGetSymbolAddress((void**)&p_ctr,    g_ctr);
    cudaGetSymbolAddress((void**)&p_dis,    g_dis);
    cudaGetSymbolAddress((void**)&p_h,      g_h);
    cudaGetSymbolAddress((void**)&p_t,      g_t);

    const int T = 256;

    // ---- CSR build (4 launches) ----
    k_zero<<<(n + T - 1) / T, T>>>(p_cnt, p_ctr, n);
    k_hist<<<(E / 8 + T - 1) / T, T>>>(cols, p_cnt, E);
    k_offset<<<(n + 1023) / 1024, 1024>>>(p_cnt, p_start, p_cursor, p_dis, p_ctr, n);
    k_build<<<(E / 4 + T - 1) / T, T>>>(rows, cols, p_cursor, p_adj, E);

    const int gemm_grid = (n + 255) / 256;
    const int gath_grid = (int)(((long long)n * 8 + T - 1) / T);

    // ---- layer 1 ----
    k_gemm<<<gemm_grid, T>>>(x, W1, p_dis, p_h, n);
    k_gather<true><<<gath_grid, T>>>(p_start, p_cnt, p_adj, p_h, p_dis, b1, p_t, n);

    // ---- layer 2 ----
    k_gemm<<<gemm_grid, T>>>(p_t, W2, p_dis, p_h, n);
    k_gather<false><<<gath_grid, T>>>(p_start, p_cnt, p_adj, p_h, p_dis, b2, outp, n);
}

// round 9
// speedup vs baseline: 1.9335x; 1.0214x over previous
#include <cuda_runtime.h>
#include <stdint.h>

// SimpleGCN: 2-layer GCN, N=100000 nodes, C=32, E=1.6M edges (int32).
// out = GCNConv2( relu( GCNConv1(x) ) ), self-loops, symmetric norm.
//
// Pull-mode with fixed-capacity adjacency buckets (no scan, no packed CSR):
//   slot = atomicAdd(cnt[col]);  adj[col*CAP + slot] = row;
//   h~ = dis * (in @ W),  dis[i] = rsqrt(1 + cnt[i])   (computed inline)
//   out[i] = act( b + dis[i] * ( h~[i] + sum_j h~[adj[i][j]] ) )
// Degrees ~ Poisson(16) -> CAP=128 is ~60 sigma of margin (clamped anyway).

#define GCN_N 100000
#define GCN_C 32
#define GCN_CAP 128

__device__ int g_cnt[GCN_N];                           // in-degree (excl self)
__device__ int g_adj[(size_t)GCN_N * GCN_CAP];         // bucketed adjacency
__device__ __align__(16) float g_h[GCN_N * GCN_C];     // dis * (in @ W)
__device__ __align__(16) float g_t[GCN_N * GCN_C];     // layer-1 activations

// ---------------------------------------------------------------------------
// Bucket build
// ---------------------------------------------------------------------------
__global__ void k_zero(int* __restrict__ cnt, int n) {
    int i = blockIdx.x * blockDim.x + threadIdx.x;
    if (i < n) cnt[i] = 0;
}

__global__ __launch_bounds__(256) void k_fill(
    const int* __restrict__ row, const int* __restrict__ col,
    int* __restrict__ cnt, int* __restrict__ adj, int E)
{
    int i = (blockIdx.x * blockDim.x + threadIdx.x) * 8;
    if (i + 7 < E) {
        int4 c0 = *(const int4*)(col + i);
        int4 c1 = *(const int4*)(col + i + 4);
        int4 r0 = *(const int4*)(row + i);
        int4 r1 = *(const int4*)(row + i + 4);
        // 8 independent atomic reservations in flight
        int s0 = atomicAdd(&cnt[c0.x], 1);
        int s1 = atomicAdd(&cnt[c0.y], 1);
        int s2 = atomicAdd(&cnt[c0.z], 1);
        int s3 = atomicAdd(&cnt[c0.w], 1);
        int s4 = atomicAdd(&cnt[c1.x], 1);
        int s5 = atomicAdd(&cnt[c1.y], 1);
        int s6 = atomicAdd(&cnt[c1.z], 1);
        int s7 = atomicAdd(&cnt[c1.w], 1);
        if (s0 < GCN_CAP) adj[(size_t)c0.x * GCN_CAP + s0] = r0.x;
        if (s1 < GCN_CAP) adj[(size_t)c0.y * GCN_CAP + s1] = r0.y;
        if (s2 < GCN_CAP) adj[(size_t)c0.z * GCN_CAP + s2] = r0.z;
        if (s3 < GCN_CAP) adj[(size_t)c0.w * GCN_CAP + s3] = r0.w;
        if (s4 < GCN_CAP) adj[(size_t)c1.x * GCN_CAP + s4] = r1.x;
        if (s5 < GCN_CAP) adj[(size_t)c1.y * GCN_CAP + s5] = r1.y;
        if (s6 < GCN_CAP) adj[(size_t)c1.z * GCN_CAP + s6] = r1.z;
        if (s7 < GCN_CAP) adj[(size_t)c1.w * GCN_CAP + s7] = r1.w;
    } else {
        for (int e = i; e < E; e++) {
            int c = col[e];
            int s = atomicAdd(&cnt[c], 1);
            if (s < GCN_CAP) adj[(size_t)c * GCN_CAP + s] = row[e];
        }
    }
}

// ---------------------------------------------------------------------------
// Register-tiled GEMM: h~ = rsqrt(1+cnt) * (in @ W).
// 256 nodes/block, thread tile 2 x (4 nodes x 4 ch), XOR-swizzled shared.
// ---------------------------------------------------------------------------
__global__ __launch_bounds__(256) void k_gemm(
    const float* __restrict__ in, const float* __restrict__ W,
    const int* __restrict__ cnt, float* __restrict__ h, int n)
{
    __shared__ float xT[32][256];   // [k][swizzled node]
    __shared__ float Ws[32 * 32];   // row-major [k][c]
    __shared__ float disS[256];

    const int tid = threadIdx.x;
    const int base = blockIdx.x * 256;

    ((float4*)Ws)[tid] = ((const float4*)W)[tid];
    {
        int node = base + tid;
        disS[tid] = (node < n) ? rsqrtf(1.0f + (float)cnt[node]) : 0.0f;
    }

    #pragma unroll
    for (int l = 0; l < 8; l++) {
        int i = tid + l * 256;
        int node = i >> 3;          // 0..255
        int kc = (i & 7) * 4;       // 0,4,...,28
        float4 v = make_float4(0.f, 0.f, 0.f, 0.f);
        if (base + node < n)
            v = *(const float4*)(in + (size_t)(base + node) * GCN_C + kc);
        int sc = node ^ kc;
        xT[kc + 0][sc] = v.x;
        xT[kc + 1][sc] = v.y;
        xT[kc + 2][sc] = v.z;
        xT[kc + 3][sc] = v.w;
    }
    __syncthreads();

    const int tn = (tid & 31) * 4;
    const int tc = (tid >> 5) * 4;

    float4 l0 = {0,0,0,0}, l1 = {0,0,0,0}, l2 = {0,0,0,0}, l3 = {0,0,0,0};
    float4 u0 = {0,0,0,0}, u1 = {0,0,0,0}, u2 = {0,0,0,0}, u3 = {0,0,0,0};

    #pragma unroll
    for (int k = 0; k < 32; k++) {
        const int s = k & 28;
        float4 a = *(const float4*)&xT[k][tn ^ s];
        float4 c = *(const float4*)&xT[k][(tn + 128) ^ s];
        float4 w = *(const float4*)&Ws[k * 32 + tc];
        l0.x = fmaf(a.x, w.x, l0.x); l0.y = fmaf(a.x, w.y, l0.y);
        l0.z = fmaf(a.x, w.z, l0.z); l0.w = fmaf(a.x, w.w, l0.w);
        l1.x = fmaf(a.y, w.x, l1.x); l1.y = fmaf(a.y, w.y, l1.y);
        l1.z = fmaf(a.y, w.z, l1.z); l1.w = fmaf(a.y, w.w, l1.w);
        l2.x = fmaf(a.z, w.x, l2.x); l2.y = fmaf(a.z, w.y, l2.y);
        l2.z = fmaf(a.z, w.z, l2.z); l2.w = fmaf(a.z, w.w, l2.w);
        l3.x = fmaf(a.w, w.x, l3.x); l3.y = fmaf(a.w, w.y, l3.y);
        l3.z = fmaf(a.w, w.z, l3.z); l3.w = fmaf(a.w, w.w, l3.w);
        u0.x = fmaf(c.x, w.x, u0.x); u0.y = fmaf(c.x, w.y, u0.y);
        u0.z = fmaf(c.x, w.z, u0.z); u0.w = fmaf(c.x, w.w, u0.w);
        u1.x = fmaf(c.y, w.x, u1.x); u1.y = fmaf(c.y, w.y, u1.y);
        u1.z = fmaf(c.y, w.z, u1.z); u1.w = fmaf(c.y, w.w, u1.w);
        u2.x = fmaf(c.z, w.x, u2.x); u2.y = fmaf(c.z, w.y, u2.y);
        u2.z = fmaf(c.z, w.z, u2.z); u2.w = fmaf(c.z, w.w, u2.w);
        u3.x = fmaf(c.w, w.x, u3.x); u3.y = fmaf(c.w, w.y, u3.y);
        u3.z = fmaf(c.w, w.z, u3.z); u3.w = fmaf(c.w, w.w, u3.w);
    }

    float4 lo[4] = {l0, l1, l2, l3};
    float4 hi[4] = {u0, u1, u2, u3};
    #pragma unroll
    for (int i = 0; i < 4; i++) {
        int ln = tn + i;
        int node = base + ln;
        if (node < n) {
            float d = disS[ln];
            float4 hv = lo[i];
            hv.x *= d; hv.y *= d; hv.z *= d; hv.w *= d;
            *(float4*)(h + (size_t)node * GCN_C + tc) = hv;
        }
        int un = tn + 128 + i;
        int node2 = base + un;
        if (node2 < n) {
            float d = disS[un];
            float4 hv = hi[i];
            hv.x *= d; hv.y *= d; hv.z *= d; hv.w *= d;
            *(float4*)(h + (size_t)node2 * GCN_C + tc) = hv;
        }
    }
}

// ---------------------------------------------------------------------------
// Pull-mode aggregation: 8-lane team per destination node.
//   acc = h~[i] + sum_{j < cnt[i]} h~[ adj[i*CAP + j] ]
//   out = (RELU? relu : id)( b[c] + rsqrt(1+cnt[i]) * acc )
// x4-unrolled independent gathers -> MLP 4/thread.
// ---------------------------------------------------------------------------
template <bool RELU>
__global__ __launch_bounds__(256) void k_gather(
    const int* __restrict__ cnt, const int* __restrict__ adj,
    const float* __restrict__ h,
    const float* __restrict__ b, float* __restrict__ out, int n)
{
    long long tid = (long long)blockIdx.x * blockDim.x + threadIdx.x;
    int node = (int)(tid >> 3);
    if (node >= n) return;
    const int off = (int)(tid & 7) * 4;

    int cv = cnt[node];
    int end = (cv < GCN_CAP) ? cv : GCN_CAP;
    float d = rsqrtf(1.0f + (float)cv);
    const int* list = adj + (size_t)node * GCN_CAP;

    float4 acc = *(const float4*)(h + (size_t)node * GCN_C + off);  // self-loop

    int j = 0;
    for (; j + 4 <= end; j += 4) {
        int s0 = list[j], s1 = list[j + 1], s2 = list[j + 2], s3 = list[j + 3];
        float4 m0 = __ldg((const float4*)(h + (size_t)s0 * GCN_C + off));
        float4 m1 = __ldg((const float4*)(h + (size_t)s1 * GCN_C + off));
        float4 m2 = __ldg((const float4*)(h + (size_t)s2 * GCN_C + off));
        float4 m3 = __ldg((const float4*)(h + (size_t)s3 * GCN_C + off));
        acc.x += (m0.x + m1.x) + (m2.x + m3.x);
        acc.y += (m0.y + m1.y) + (m2.y + m3.y);
        acc.z += (m0.z + m1.z) + (m2.z + m3.z);
        acc.w += (m0.w + m1.w) + (m2.w + m3.w);
    }
    for (; j < end; j++) {
        int s = list[j];
        float4 m = __ldg((const float4*)(h + (size_t)s * GCN_C + off));
        acc.x += m.x; acc.y += m.y; acc.z += m.z; acc.w += m.w;
    }

    float4 bi = __ldg((const float4*)(b + off));
    float4 o;
    o.x = fmaf(d, acc.x, bi.x);
    o.y = fmaf(d, acc.y, bi.y);
    o.z = fmaf(d, acc.z, bi.z);
    o.w = fmaf(d, acc.w, bi.w);
    if (RELU) {
        o.x = fmaxf(o.x, 0.f); o.y = fmaxf(o.y, 0.f);
        o.z = fmaxf(o.z, 0.f); o.w = fmaxf(o.w, 0.f);
    }
    *(float4*)(out + (size_t)node * GCN_C + off) = o;
}

// ---------------------------------------------------------------------------
// Launch
// ---------------------------------------------------------------------------
extern "C" void kernel_launch(void* const* d_in, const int* in_sizes, int n_in,
                              void* d_out, int out_size)
{
    const float* x    = (const float*)d_in[0];
    const int*   ei   = (const int*)d_in[1];
    const float* W1   = (const float*)d_in[2];
    const float* b1   = (const float*)d_in[3];
    const float* W2   = (const float*)d_in[4];
    const float* b2   = (const float*)d_in[5];
    float*       outp = (float*)d_out;

    const int E = in_sizes[1] / 2;
    const int* rows = ei;
    const int* cols = ei + E;
    const int n = GCN_N;

    int *p_cnt, *p_adj;
    float *p_h, *p_t;
    cudaGetSymbolAddress((void**)&p_cnt, g_cnt);
    cudaGetSymbolAddress((void**)&p_adj, g_adj);
    cudaGetSymbolAddress((void**)&p_h,   g_h);
    cudaGetSymbolAddress((void**)&p_t,   g_t);

    const int T = 256;

    // ---- bucket build (2 launches) ----
    k_zero<<<(n + T - 1) / T, T>>>(p_cnt, n);
    k_fill<<<(E / 8 + T - 1) / T, T>>>(rows, cols, p_cnt, p_adj, E);

    const int gemm_grid = (n + 255) / 256;
    const int gath_grid = (int)(((long long)n * 8 + T - 1) / T);

    // ---- layer 1 ----
    k_gemm<<<gemm_grid, T>>>(x, W1, p_cnt, p_h, n);
    k_gather<true><<<gath_grid, T>>>(p_cnt, p_adj, p_h, b1, p_t, n);

    // ---- layer 2 ----
    k_gemm<<<gemm_grid, T>>>(p_t, W2, p_cnt, p_h, n);
    k_gather<false><<<gath_grid, T>>>(p_cnt, p_adj, p_h, b2, outp, n);
}

// round 10
// speedup vs baseline: 2.0690x; 1.0701x over previous
#include <cuda_runtime.h>
#include <cuda_fp16.h>
#include <stdint.h>

// SimpleGCN: 2-layer GCN, N=100000 nodes, C=32, E=1.6M edges (int32).
// out = GCNConv2( relu( GCNConv1(x) ) ), self-loops, symmetric norm.
//
// Pull-mode, fixed-capacity adjacency buckets, fp16 message features:
//   slot = atomicAdd(cnt[col]);  adj[col*CAP + slot] = row;
//   h~ = fp16( dis * (in @ W) ),  dis[i] = rsqrt(1 + cnt[i])
//   out[i] = act( b + dis[i] * ( h~[i] + sum_j h~[adj[i][j]] ) )   (fp32 accum)

#define GCN_N 100000
#define GCN_C 32
#define GCN_CAP 64

__device__ int g_cnt[GCN_N];                            // in-degree (excl self)
__device__ int g_adj[(size_t)GCN_N * GCN_CAP];          // bucketed adjacency
__device__ __align__(16) __half g_h[GCN_N * GCN_C];     // fp16 dis*(in@W)
__device__ __align__(16) float  g_t[GCN_N * GCN_C];     // layer-1 activations

// ---------------------------------------------------------------------------
// Bucket build
// ---------------------------------------------------------------------------
__global__ void k_zero(int* __restrict__ cnt, int n) {
    int i = blockIdx.x * blockDim.x + threadIdx.x;
    if (i < n) cnt[i] = 0;
}

__global__ __launch_bounds__(256) void k_fill(
    const int* __restrict__ row, const int* __restrict__ col,
    int* __restrict__ cnt, int* __restrict__ adj, int E)
{
    int i = (blockIdx.x * blockDim.x + threadIdx.x) * 8;
    if (i + 7 < E) {
        int4 c0 = *(const int4*)(col + i);
        int4 c1 = *(const int4*)(col + i + 4);
        int4 r0 = *(const int4*)(row + i);
        int4 r1 = *(const int4*)(row + i + 4);
        int s0 = atomicAdd(&cnt[c0.x], 1);
        int s1 = atomicAdd(&cnt[c0.y], 1);
        int s2 = atomicAdd(&cnt[c0.z], 1);
        int s3 = atomicAdd(&cnt[c0.w], 1);
        int s4 = atomicAdd(&cnt[c1.x], 1);
        int s5 = atomicAdd(&cnt[c1.y], 1);
        int s6 = atomicAdd(&cnt[c1.z], 1);
        int s7 = atomicAdd(&cnt[c1.w], 1);
        if (s0 < GCN_CAP) adj[(size_t)c0.x * GCN_CAP + s0] = r0.x;
        if (s1 < GCN_CAP) adj[(size_t)c0.y * GCN_CAP + s1] = r0.y;
        if (s2 < GCN_CAP) adj[(size_t)c0.z * GCN_CAP + s2] = r0.z;
        if (s3 < GCN_CAP) adj[(size_t)c0.w * GCN_CAP + s3] = r0.w;
        if (s4 < GCN_CAP) adj[(size_t)c1.x * GCN_CAP + s4] = r1.x;
        if (s5 < GCN_CAP) adj[(size_t)c1.y * GCN_CAP + s5] = r1.y;
        if (s6 < GCN_CAP) adj[(size_t)c1.z * GCN_CAP + s6] = r1.z;
        if (s7 < GCN_CAP) adj[(size_t)c1.w * GCN_CAP + s7] = r1.w;
    } else {
        for (int e = i; e < E; e++) {
            int c = col[e];
            int s = atomicAdd(&cnt[c], 1);
            if (s < GCN_CAP) adj[(size_t)c * GCN_CAP + s] = row[e];
        }
    }
}

// ---------------------------------------------------------------------------
// Register-tiled GEMM: h~ = fp16( rsqrt(1+cnt) * (in @ W) ).
// 256 nodes/block, thread tile 2 x (4 nodes x 4 ch), XOR-swizzled shared.
// ---------------------------------------------------------------------------
__global__ __launch_bounds__(256) void k_gemm(
    const float* __restrict__ in, const float* __restrict__ W,
    const int* __restrict__ cnt, __half* __restrict__ h, int n)
{
    __shared__ float xT[32][256];   // [k][swizzled node]
    __shared__ float Ws[32 * 32];   // row-major [k][c]
    __shared__ float disS[256];

    const int tid = threadIdx.x;
    const int base = blockIdx.x * 256;

    ((float4*)Ws)[tid] = ((const float4*)W)[tid];
    {
        int node = base + tid;
        disS[tid] = (node < n) ? rsqrtf(1.0f + (float)cnt[node]) : 0.0f;
    }

    #pragma unroll
    for (int l = 0; l < 8; l++) {
        int i = tid + l * 256;
        int node = i >> 3;          // 0..255
        int kc = (i & 7) * 4;       // 0,4,...,28
        float4 v = make_float4(0.f, 0.f, 0.f, 0.f);
        if (base + node < n)
            v = *(const float4*)(in + (size_t)(base + node) * GCN_C + kc);
        int sc = node ^ kc;
        xT[kc + 0][sc] = v.x;
        xT[kc + 1][sc] = v.y;
        xT[kc + 2][sc] = v.z;
        xT[kc + 3][sc] = v.w;
    }
    __syncthreads();

    const int tn = (tid & 31) * 4;
    const int tc = (tid >> 5) * 4;

    float4 l0 = {0,0,0,0}, l1 = {0,0,0,0}, l2 = {0,0,0,0}, l3 = {0,0,0,0};
    float4 u0 = {0,0,0,0}, u1 = {0,0,0,0}, u2 = {0,0,0,0}, u3 = {0,0,0,0};

    #pragma unroll
    for (int k = 0; k < 32; k++) {
        const int s = k & 28;
        float4 a = *(const float4*)&xT[k][tn ^ s];
        float4 c = *(const float4*)&xT[k][(tn + 128) ^ s];
        float4 w = *(const float4*)&Ws[k * 32 + tc];
        l0.x = fmaf(a.x, w.x, l0.x); l0.y = fmaf(a.x, w.y, l0.y);
        l0.z = fmaf(a.x, w.z, l0.z); l0.w = fmaf(a.x, w.w, l0.w);
        l1.x = fmaf(a.y, w.x, l1.x); l1.y = fmaf(a.y, w.y, l1.y);
        l1.z = fmaf(a.y, w.z, l1.z); l1.w = fmaf(a.y, w.w, l1.w);
        l2.x = fmaf(a.z, w.x, l2.x); l2.y = fmaf(a.z, w.y, l2.y);
        l2.z = fmaf(a.z, w.z, l2.z); l2.w = fmaf(a.z, w.w, l2.w);
        l3.x = fmaf(a.w, w.x, l3.x); l3.y = fmaf(a.w, w.y, l3.y);
        l3.z = fmaf(a.w, w.z, l3.z); l3.w = fmaf(a.w, w.w, l3.w);
        u0.x = fmaf(c.x, w.x, u0.x); u0.y = fmaf(c.x, w.y, u0.y);
        u0.z = fmaf(c.x, w.z, u0.z); u0.w = fmaf(c.x, w.w, u0.w);
        u1.x = fmaf(c.y, w.x, u1.x); u1.y = fmaf(c.y, w.y, u1.y);
        u1.z = fmaf(c.y, w.z, u1.z); u1.w = fmaf(c.y, w.w, u1.w);
        u2.x = fmaf(c.z, w.x, u2.x); u2.y = fmaf(c.z, w.y, u2.y);
        u2.z = fmaf(c.z, w.z, u2.z); u2.w = fmaf(c.z, w.w, u2.w);
        u3.x = fmaf(c.w, w.x, u3.x); u3.y = fmaf(c.w, w.y, u3.y);
        u3.z = fmaf(c.w, w.z, u3.z); u3.w = fmaf(c.w, w.w, u3.w);
    }

    float4 lo[4] = {l0, l1, l2, l3};
    float4 hi[4] = {u0, u1, u2, u3};
    #pragma unroll
    for (int i = 0; i < 4; i++) {
        #pragma unroll
        for (int half_sel = 0; half_sel < 2; half_sel++) {
            int ln = tn + i + half_sel * 128;
            int node = base + ln;
            if (node < n) {
                float d = disS[ln];
                float4 hv = half_sel ? hi[i] : lo[i];
                __half2 p0 = __floats2half2_rn(d * hv.x, d * hv.y);
                __half2 p1 = __floats2half2_rn(d * hv.z, d * hv.w);
                uint2 pk;
                pk.x = *(uint32_t*)&p0;
                pk.y = *(uint32_t*)&p1;
                *(uint2*)(h + (size_t)node * GCN_C + tc) = pk;  // 8B store
            }
        }
    }
}

// ---------------------------------------------------------------------------
// Pull-mode aggregation: 4-lane team per destination node, 8 halves per lane.
//   acc(fp32) = h~[i] + sum_{j < cnt[i]} h~[ adj[i*CAP + j] ]
//   out = (RELU? relu : id)( b[c] + rsqrt(1+cnt[i]) * acc )
// x4-unrolled independent 16B gathers -> MLP 4/thread.
// ---------------------------------------------------------------------------
template <bool RELU>
__global__ __launch_bounds__(256) void k_gather(
    const int* __restrict__ cnt, const int* __restrict__ adj,
    const __half* __restrict__ h,
    const float* __restrict__ b, float* __restrict__ out, int n)
{
    long long tid = (long long)blockIdx.x * blockDim.x + threadIdx.x;
    int node = (int)(tid >> 2);
    if (node >= n) return;
    const int sub = (int)(tid & 3);
    const int hoff = sub * 8;               // halves offset in row

    int cv = cnt[node];
    int end = (cv < GCN_CAP) ? cv : GCN_CAP;
    float d = rsqrtf(1.0f + (float)cv);
    const int* list = adj + (size_t)node * GCN_CAP;

    // self-loop seed
    float2 a0, a1, a2, a3;
    {
        uint4 sv = *(const uint4*)(h + (size_t)node * GCN_C + hoff);
        a0 = __half22float2(*(__half2*)&sv.x);
        a1 = __half22float2(*(__half2*)&sv.y);
        a2 = __half22float2(*(__half2*)&sv.z);
        a3 = __half22float2(*(__half2*)&sv.w);
    }

    int j = 0;
    for (; j + 4 <= end; j += 4) {
        int s0 = list[j], s1 = list[j + 1], s2 = list[j + 2], s3 = list[j + 3];
        uint4 v0 = __ldg((const uint4*)(h + (size_t)s0 * GCN_C + hoff));
        uint4 v1 = __ldg((const uint4*)(h + (size_t)s1 * GCN_C + hoff));
        uint4 v2 = __ldg((const uint4*)(h + (size_t)s2 * GCN_C + hoff));
        uint4 v3 = __ldg((const uint4*)(h + (size_t)s3 * GCN_C + hoff));
        #define ACC8(v) do { \
            float2 f0 = __half22float2(*(__half2*)&(v).x); \
            float2 f1 = __half22float2(*(__half2*)&(v).y); \
            float2 f2 = __half22float2(*(__half2*)&(v).z); \
            float2 f3 = __half22float2(*(__half2*)&(v).w); \
            a0.x += f0.x; a0.y += f0.y; a1.x += f1.x; a1.y += f1.y; \
            a2.x += f2.x; a2.y += f2.y; a3.x += f3.x; a3.y += f3.y; } while (0)
        ACC8(v0); ACC8(v1); ACC8(v2); ACC8(v3);
    }
    for (; j < end; j++) {
        int s = list[j];
        uint4 v = __ldg((const uint4*)(h + (size_t)s * GCN_C + hoff));
        ACC8(v);
    }
    #undef ACC8

    const int foff = sub * 8;               // float offset in output row
    float4 bi0 = *(const float4*)(b + foff);
    float4 bi1 = *(const float4*)(b + foff + 4);
    float4 o0, o1;
    o0.x = fmaf(d, a0.x, bi0.x); o0.y = fmaf(d, a0.y, bi0.y);
    o0.z = fmaf(d, a1.x, bi0.z); o0.w = fmaf(d, a1.y, bi0.w);
    o1.x = fmaf(d, a2.x, bi1.x); o1.y = fmaf(d, a2.y, bi1.y);
    o1.z = fmaf(d, a3.x, bi1.z); o1.w = fmaf(d, a3.y, bi1.w);
    if (RELU) {
        o0.x = fmaxf(o0.x, 0.f); o0.y = fmaxf(o0.y, 0.f);
        o0.z = fmaxf(o0.z, 0.f); o0.w = fmaxf(o0.w, 0.f);
        o1.x = fmaxf(o1.x, 0.f); o1.y = fmaxf(o1.y, 0.f);
        o1.z = fmaxf(o1.z, 0.f); o1.w = fmaxf(o1.w, 0.f);
    }
    *(float4*)(out + (size_t)node * GCN_C + foff) = o0;
    *(float4*)(out + (size_t)node * GCN_C + foff + 4) = o1;
}

// ---------------------------------------------------------------------------
// Launch
// ---------------------------------------------------------------------------
extern "C" void kernel_launch(void* const* d_in, const int* in_sizes, int n_in,
                              void* d_out, int out_size)
{
    const float* x    = (const float*)d_in[0];
    const int*   ei   = (const int*)d_in[1];
    const float* W1   = (const float*)d_in[2];
    const float* b1   = (const float*)d_in[3];
    const float* W2   = (const float*)d_in[4];
    const float* b2   = (const float*)d_in[5];
    float*       outp = (float*)d_out;

    const int E = in_sizes[1] / 2;
    const int* rows = ei;
    const int* cols = ei + E;
    const int n = GCN_N;

    int *p_cnt, *p_adj;
    __half* p_h;
    float* p_t;
    cudaGetSymbolAddress((void**)&p_cnt, g_cnt);
    cudaGetSymbolAddress((void**)&p_adj, g_adj);
    cudaGetSymbolAddress((void**)&p_h,   g_h);
    cudaGetSymbolAddress((void**)&p_t,   g_t);

    const int T = 256;

    // ---- bucket build ----
    k_zero<<<(n + T - 1) / T, T>>>(p_cnt, n);
    k_fill<<<(E / 8 + T - 1) / T, T>>>(rows, cols, p_cnt, p_adj, E);

    const int gemm_grid = (n + 255) / 256;
    const int gath_grid = (int)(((long long)n * 4 + T - 1) / T);

    // ---- layer 1 ----
    k_gemm<<<gemm_grid, T>>>(x, W1, p_cnt, p_h, n);
    k_gather<true><<<gath_grid, T>>>(p_cnt, p_adj, p_h, b1, p_t, n);

    // ---- layer 2 ----
    k_gemm<<<gemm_grid, T>>>(p_t, W2, p_cnt, p_h, n);
    k_gather<false><<<gath_grid, T>>>(p_cnt, p_adj, p_h, b2, outp, n);
}

// round 11
// speedup vs baseline: 2.2241x; 1.0750x over previous
#include <cuda_runtime.h>
#include <cuda_fp16.h>
#include <stdint.h>

// SimpleGCN: 2-layer GCN, N=100000 nodes, C=32, E=1.6M edges (int32).
// out = GCNConv2( relu( GCNConv1(x) ) ), self-loops, symmetric norm.
//
// Pull-mode, fixed-capacity adjacency buckets, fp16 message features.
// Layer-1 aggregation is FUSED with the layer-2 GEMM (gather feeds the
// shared-memory GEMM tile directly; no intermediate global round-trip).

#define GCN_N 100000
#define GCN_C 32
#define GCN_CAP 64

__device__ int g_cnt[GCN_N];                            // in-degree (excl self)
__device__ int g_adj[(size_t)GCN_N * GCN_CAP];          // bucketed adjacency
__device__ __align__(16) __half g_h1[GCN_N * GCN_C];    // fp16 dis*(x@W1)
__device__ __align__(16) __half g_h2[GCN_N * GCN_C];    // fp16 dis*(relu@W2)

// ---------------------------------------------------------------------------
// Bucket build
// ---------------------------------------------------------------------------
__global__ void k_zero(int* __restrict__ cnt, int n) {
    int i = blockIdx.x * blockDim.x + threadIdx.x;
    if (i < n) cnt[i] = 0;
}

__global__ __launch_bounds__(256) void k_fill(
    const int* __restrict__ row, const int* __restrict__ col,
    int* __restrict__ cnt, int* __restrict__ adj, int E)
{
    int i = (blockIdx.x * blockDim.x + threadIdx.x) * 8;
    if (i + 7 < E) {
        int4 c0 = *(const int4*)(col + i);
        int4 c1 = *(const int4*)(col + i + 4);
        int4 r0 = *(const int4*)(row + i);
        int4 r1 = *(const int4*)(row + i + 4);
        int s0 = atomicAdd(&cnt[c0.x], 1);
        int s1 = atomicAdd(&cnt[c0.y], 1);
        int s2 = atomicAdd(&cnt[c0.z], 1);
        int s3 = atomicAdd(&cnt[c0.w], 1);
        int s4 = atomicAdd(&cnt[c1.x], 1);
        int s5 = atomicAdd(&cnt[c1.y], 1);
        int s6 = atomicAdd(&cnt[c1.z], 1);
        int s7 = atomicAdd(&cnt[c1.w], 1);
        if (s0 < GCN_CAP) adj[(size_t)c0.x * GCN_CAP + s0] = r0.x;
        if (s1 < GCN_CAP) adj[(size_t)c0.y * GCN_CAP + s1] = r0.y;
        if (s2 < GCN_CAP) adj[(size_t)c0.z * GCN_CAP + s2] = r0.z;
        if (s3 < GCN_CAP) adj[(size_t)c0.w * GCN_CAP + s3] = r0.w;
        if (s4 < GCN_CAP) adj[(size_t)c1.x * GCN_CAP + s4] = r1.x;
        if (s5 < GCN_CAP) adj[(size_t)c1.y * GCN_CAP + s5] = r1.y;
        if (s6 < GCN_CAP) adj[(size_t)c1.z * GCN_CAP + s6] = r1.z;
        if (s7 < GCN_CAP) adj[(size_t)c1.w * GCN_CAP + s7] = r1.w;
    } else {
        for (int e = i; e < E; e++) {
            int c = col[e];
            int s = atomicAdd(&cnt[c], 1);
            if (s < GCN_CAP) adj[(size_t)c * GCN_CAP + s] = row[e];
        }
    }
}

// ---------------------------------------------------------------------------
// GEMM compute core (shared tiles -> fp16 h out). Used by both GEMM kernels.
// Thread tile 2 x (4 nodes x 4 ch); xT is XOR-swizzled [k][node^(k&28)].
// ---------------------------------------------------------------------------
__device__ __forceinline__ void gemm_core(
    const float (*xT)[256], const float* Ws, const float* disS,
    __half* __restrict__ h, int base, int n, int tid)
{
    const int tn = (tid & 31) * 4;
    const int tc = (tid >> 5) * 4;

    float4 l0 = {0,0,0,0}, l1 = {0,0,0,0}, l2 = {0,0,0,0}, l3 = {0,0,0,0};
    float4 u0 = {0,0,0,0}, u1 = {0,0,0,0}, u2 = {0,0,0,0}, u3 = {0,0,0,0};

    #pragma unroll
    for (int k = 0; k < 32; k++) {
        const int s = k & 28;
        float4 a = *(const float4*)&xT[k][tn ^ s];
        float4 c = *(const float4*)&xT[k][(tn + 128) ^ s];
        float4 w = *(const float4*)&Ws[k * 32 + tc];
        l0.x = fmaf(a.x, w.x, l0.x); l0.y = fmaf(a.x, w.y, l0.y);
        l0.z = fmaf(a.x, w.z, l0.z); l0.w = fmaf(a.x, w.w, l0.w);
        l1.x = fmaf(a.y, w.x, l1.x); l1.y = fmaf(a.y, w.y, l1.y);
        l1.z = fmaf(a.y, w.z, l1.z); l1.w = fmaf(a.y, w.w, l1.w);
        l2.x = fmaf(a.z, w.x, l2.x); l2.y = fmaf(a.z, w.y, l2.y);
        l2.z = fmaf(a.z, w.z, l2.z); l2.w = fmaf(a.z, w.w, l2.w);
        l3.x = fmaf(a.w, w.x, l3.x); l3.y = fmaf(a.w, w.y, l3.y);
        l3.z = fmaf(a.w, w.z, l3.z); l3.w = fmaf(a.w, w.w, l3.w);
        u0.x = fmaf(c.x, w.x, u0.x); u0.y = fmaf(c.x, w.y, u0.y);
        u0.z = fmaf(c.x, w.z, u0.z); u0.w = fmaf(c.x, w.w, u0.w);
        u1.x = fmaf(c.y, w.x, u1.x); u1.y = fmaf(c.y, w.y, u1.y);
        u1.z = fmaf(c.y, w.z, u1.z); u1.w = fmaf(c.y, w.w, u1.w);
        u2.x = fmaf(c.z, w.x, u2.x); u2.y = fmaf(c.z, w.y, u2.y);
        u2.z = fmaf(c.z, w.z, u2.z); u2.w = fmaf(c.z, w.w, u2.w);
        u3.x = fmaf(c.w, w.x, u3.x); u3.y = fmaf(c.w, w.y, u3.y);
        u3.z = fmaf(c.w, w.z, u3.z); u3.w = fmaf(c.w, w.w, u3.w);
    }

    float4 lo[4] = {l0, l1, l2, l3};
    float4 hi[4] = {u0, u1, u2, u3};
    #pragma unroll
    for (int i = 0; i < 4; i++) {
        #pragma unroll
        for (int hs = 0; hs < 2; hs++) {
            int ln = tn + i + hs * 128;
            int node = base + ln;
            if (node < n) {
                float d = disS[ln];
                float4 hv = hs ? hi[i] : lo[i];
                __half2 p0 = __floats2half2_rn(d * hv.x, d * hv.y);
                __half2 p1 = __floats2half2_rn(d * hv.z, d * hv.w);
                uint2 pk;
                pk.x = *(uint32_t*)&p0;
                pk.y = *(uint32_t*)&p1;
                *(uint2*)(h + (size_t)node * GCN_C + tc) = pk;
            }
        }
    }
}

// ---------------------------------------------------------------------------
// Layer-1 GEMM: h1 = fp16( dis * (x @ W1) ). Input staged from global fp32.
// ---------------------------------------------------------------------------
__global__ __launch_bounds__(256) void k_gemm1(
    const float* __restrict__ in, const float* __restrict__ W,
    const int* __restrict__ cnt, __half* __restrict__ h, int n)
{
    __shared__ float xT[32][256];
    __shared__ float Ws[32 * 32];
    __shared__ float disS[256];

    const int tid = threadIdx.x;
    const int base = blockIdx.x * 256;

    ((float4*)Ws)[tid] = ((const float4*)W)[tid];
    {
        int node = base + tid;
        disS[tid] = (node < n) ? rsqrtf(1.0f + (float)cnt[node]) : 0.0f;
    }

    #pragma unroll
    for (int l = 0; l < 8; l++) {
        int i = tid + l * 256;
        int node = i >> 3;
        int kc = (i & 7) * 4;
        float4 v = make_float4(0.f, 0.f, 0.f, 0.f);
        if (base + node < n)
            v = *(const float4*)(in + (size_t)(base + node) * GCN_C + kc);
        int sc = node ^ kc;
        xT[kc + 0][sc] = v.x;
        xT[kc + 1][sc] = v.y;
        xT[kc + 2][sc] = v.z;
        xT[kc + 3][sc] = v.w;
    }
    __syncthreads();

    gemm_core(xT, Ws, disS, h, base, n, tid);
}

// ---------------------------------------------------------------------------
// FUSED: layer-1 aggregation + layer-2 GEMM.
// Phase 1: 4 lanes/node gather h1 neighbors (fp32 accum), apply
//          relu(b1 + dis*acc), write straight into the swizzled xT tile.
// Phase 2: GEMM core -> h2 = fp16( dis * (relu_tile @ W2) ).
// ---------------------------------------------------------------------------
__global__ __launch_bounds__(256) void k_fuse(
    const int* __restrict__ cnt, const int* __restrict__ adj,
    const __half* __restrict__ h1, const float* __restrict__ b1,
    const float* __restrict__ W2, __half* __restrict__ h2, int n)
{
    __shared__ float xT[32][256];
    __shared__ float Ws[32 * 32];
    __shared__ float disS[256];
    __shared__ int   cntS[256];

    const int tid = threadIdx.x;
    const int base = blockIdx.x * 256;

    ((float4*)Ws)[tid] = ((const float4*)W2)[tid];
    {
        int node = base + tid;
        int cv = (node < n) ? cnt[node] : 0;
        cntS[tid] = cv;
        disS[tid] = rsqrtf(1.0f + (float)cv);
    }
    __syncthreads();

    // ---- Phase 1: gather -> relu -> xT ----
    const int lane_node = tid >> 2;          // 0..63
    const int sub = tid & 3;
    const int hoff = sub * 8;                // halves offset in h1 row
    const float4 bi0 = *(const float4*)(b1 + hoff);
    const float4 bi1 = *(const float4*)(b1 + hoff + 4);

    #pragma unroll
    for (int p = 0; p < 4; p++) {
        int nl = p * 64 + lane_node;         // node local 0..255
        int node = base + nl;

        float2 a0 = {0,0}, a1 = {0,0}, a2 = {0,0}, a3 = {0,0};
        float d = disS[nl];
        if (node < n) {
            int cv = cntS[nl];
            int end = (cv < GCN_CAP) ? cv : GCN_CAP;
            const int* list = adj + (size_t)node * GCN_CAP;

            // self-loop seed
            uint4 sv = *(const uint4*)(h1 + (size_t)node * GCN_C + hoff);
            a0 = __half22float2(*(__half2*)&sv.x);
            a1 = __half22float2(*(__half2*)&sv.y);
            a2 = __half22float2(*(__half2*)&sv.z);
            a3 = __half22float2(*(__half2*)&sv.w);

            int j = 0;
            for (; j + 4 <= end; j += 4) {
                int4 s4v = *(const int4*)(list + j);    // one 16B index load
                uint4 v0 = __ldg((const uint4*)(h1 + (size_t)s4v.x * GCN_C + hoff));
                uint4 v1 = __ldg((const uint4*)(h1 + (size_t)s4v.y * GCN_C + hoff));
                uint4 v2 = __ldg((const uint4*)(h1 + (size_t)s4v.z * GCN_C + hoff));
                uint4 v3 = __ldg((const uint4*)(h1 + (size_t)s4v.w * GCN_C + hoff));
                #define ACC8(v) do { \
                    float2 f0 = __half22float2(*(__half2*)&(v).x); \
                    float2 f1 = __half22float2(*(__half2*)&(v).y); \
                    float2 f2 = __half22float2(*(__half2*)&(v).z); \
                    float2 f3 = __half22float2(*(__half2*)&(v).w); \
                    a0.x += f0.x; a0.y += f0.y; a1.x += f1.x; a1.y += f1.y; \
                    a2.x += f2.x; a2.y += f2.y; a3.x += f3.x; a3.y += f3.y; } while (0)
                ACC8(v0); ACC8(v1); ACC8(v2); ACC8(v3);
            }
            for (; j < end; j++) {
                int s = list[j];
                uint4 v = __ldg((const uint4*)(h1 + (size_t)s * GCN_C + hoff));
                ACC8(v);
            }
        }

        // relu(b1 + d*acc) -> xT (swizzled)
        float r[8];
        r[0] = fmaxf(fmaf(d, a0.x, bi0.x), 0.f);
        r[1] = fmaxf(fmaf(d, a0.y, bi0.y), 0.f);
        r[2] = fmaxf(fmaf(d, a1.x, bi0.z), 0.f);
        r[3] = fmaxf(fmaf(d, a1.y, bi0.w), 0.f);
        r[4] = fmaxf(fmaf(d, a2.x, bi1.x), 0.f);
        r[5] = fmaxf(fmaf(d, a2.y, bi1.y), 0.f);
        r[6] = fmaxf(fmaf(d, a3.x, bi1.z), 0.f);
        r[7] = fmaxf(fmaf(d, a3.y, bi1.w), 0.f);
        #pragma unroll
        for (int jj = 0; jj < 8; jj++) {
            int k = hoff + jj;
            xT[k][nl ^ (k & 28)] = r[jj];
        }
    }
    __syncthreads();

    // ---- Phase 2: GEMM -> h2 ----
    gemm_core(xT, Ws, disS, h2, base, n, tid);
}

// ---------------------------------------------------------------------------
// Final aggregation: out = b2 + dis * ( h2[i] + sum_j h2[adj[i][j]] )
// ---------------------------------------------------------------------------
__global__ __launch_bounds__(256) void k_gather_out(
    const int* __restrict__ cnt, const int* __restrict__ adj,
    const __half* __restrict__ h,
    const float* __restrict__ b, float* __restrict__ out, int n)
{
    long long tid = (long long)blockIdx.x * blockDim.x + threadIdx.x;
    int node = (int)(tid >> 2);
    if (node >= n) return;
    const int sub = (int)(tid & 3);
    const int hoff = sub * 8;

    int cv = cnt[node];
    int end = (cv < GCN_CAP) ? cv : GCN_CAP;
    float d = rsqrtf(1.0f + (float)cv);
    const int* list = adj + (size_t)node * GCN_CAP;

    float2 a0, a1, a2, a3;
    {
        uint4 sv = *(const uint4*)(h + (size_t)node * GCN_C + hoff);
        a0 = __half22float2(*(__half2*)&sv.x);
        a1 = __half22float2(*(__half2*)&sv.y);
        a2 = __half22float2(*(__half2*)&sv.z);
        a3 = __half22float2(*(__half2*)&sv.w);
    }

    int j = 0;
    for (; j + 4 <= end; j += 4) {
        int4 s4v = *(const int4*)(list + j);
        uint4 v0 = __ldg((const uint4*)(h + (size_t)s4v.x * GCN_C + hoff));
        uint4 v1 = __ldg((const uint4*)(h + (size_t)s4v.y * GCN_C + hoff));
        uint4 v2 = __ldg((const uint4*)(h + (size_t)s4v.z * GCN_C + hoff));
        uint4 v3 = __ldg((const uint4*)(h + (size_t)s4v.w * GCN_C + hoff));
        ACC8(v0); ACC8(v1); ACC8(v2); ACC8(v3);
    }
    for (; j < end; j++) {
        int s = list[j];
        uint4 v = __ldg((const uint4*)(h + (size_t)s * GCN_C + hoff));
        ACC8(v);
    }
    #undef ACC8

    float4 bi0 = *(const float4*)(b + hoff);
    float4 bi1 = *(const float4*)(b + hoff + 4);
    float4 o0, o1;
    o0.x = fmaf(d, a0.x, bi0.x); o0.y = fmaf(d, a0.y, bi0.y);
    o0.z = fmaf(d, a1.x, bi0.z); o0.w = fmaf(d, a1.y, bi0.w);
    o1.x = fmaf(d, a2.x, bi1.x); o1.y = fmaf(d, a2.y, bi1.y);
    o1.z = fmaf(d, a3.x, bi1.z); o1.w = fmaf(d, a3.y, bi1.w);
    *(float4*)(out + (size_t)node * GCN_C + hoff) = o0;
    *(float4*)(out + (size_t)node * GCN_C + hoff + 4) = o1;
}

// ---------------------------------------------------------------------------
// Launch
// ---------------------------------------------------------------------------
extern "C" void kernel_launch(void* const* d_in, const int* in_sizes, int n_in,
                              void* d_out, int out_size)
{
    const float* x    = (const float*)d_in[0];
    const int*   ei   = (const int*)d_in[1];
    const float* W1   = (const float*)d_in[2];
    const float* b1   = (const float*)d_in[3];
    const float* W2   = (const float*)d_in[4];
    const float* b2   = (const float*)d_in[5];
    float*       outp = (float*)d_out;

    const int E = in_sizes[1] / 2;
    const int* rows = ei;
    const int* cols = ei + E;
    const int n = GCN_N;

    int *p_cnt, *p_adj;
    __half *p_h1, *p_h2;
    cudaGetSymbolAddress((void**)&p_cnt, g_cnt);
    cudaGetSymbolAddress((void**)&p_adj, g_adj);
    cudaGetSymbolAddress((void**)&p_h1,  g_h1);
    cudaGetSymbolAddress((void**)&p_h2,  g_h2);

    const int T = 256;

    // ---- bucket build ----
    k_zero<<<(n + T - 1) / T, T>>>(p_cnt, n);
    k_fill<<<(E / 8 + T - 1) / T, T>>>(rows, cols, p_cnt, p_adj, E);

    const int gemm_grid = (n + 255) / 256;
    const int gath_grid = (int)(((long long)n * 4 + T - 1) / T);

    // ---- layer 1 GEMM ----
    k_gemm1<<<gemm_grid, T>>>(x, W1, p_cnt, p_h1, n);

    // ---- fused: layer-1 aggregation + layer-2 GEMM ----
    k_fuse<<<gemm_grid, T>>>(p_cnt, p_adj, p_h1, b1, W2, p_h2, n);

    // ---- final aggregation ----
    k_gather_out<<<gath_grid, T>>>(p_cnt, p_adj, p_h2, b2, outp, n);
}